// round 11
// baseline (speedup 1.0000x reference)
#include <cuda_runtime.h>
#include <cuda_fp16.h>
#include <stdint.h>
#include <math.h>

// Problem constants
#define Bb 128
#define NQ 256
#define NC 128
#define D  1024
#define AD 256
#define HD 128
#define MD 512
#define W1N 640   // MD + HD fused N

// packed transposed weight offsets (halves)
#define W_CW  0
#define W_W1  (W_CW + 2 * AD * D)
#define W_W2  (W_W1 + 2 * W1N * AD)
#define W_TOT (W_W2 + 2 * D * MD)

// ---------------- scratch (device globals) ----------------
__device__ float  g_smooth[Bb * NQ];
__device__ float  g_common[Bb * NQ * AD];
__device__ float  g_pb[2 * W1N];
__device__ __half g_mat16[Bb * NQ * D];
__device__ __half g_q16[Bb * NQ * D];
__device__ __half g_qm16[Bb * NQ * D];
__device__ __half g_ctx16[Bb * NC * D];
__device__ __half g_ctxT16[Bb * D * NC];
__device__ __half g_attn16[Bb * NQ * NC];
__device__ __half g_d16[Bb * NQ * D];
__device__ __half g_com16[Bb * NQ * AD];
__device__ __half g_hs16[Bb * NQ * W1N];
__device__ __half g_w16[W_TOT];

// ---------------- utils ----------------
__device__ __forceinline__ float warp_sum(float v) {
#pragma unroll
    for (int o = 16; o > 0; o >>= 1) v += __shfl_xor_sync(0xffffffffu, v, o);
    return v;
}

__device__ __forceinline__ uint32_t smem_u32(const void* p) {
    uint32_t a;
    asm("{ .reg .u64 t; cvta.to.shared.u64 t, %1; cvt.u32.u64 %0, t; }" : "=r"(a) : "l"(p));
    return a;
}

__device__ __forceinline__ void cpa16(uint32_t dst, const void* src) {
    asm volatile("cp.async.cg.shared.global [%0], [%1], 16;" :: "r"(dst), "l"(src));
}
#define CPA_COMMIT() asm volatile("cp.async.commit_group;" ::: "memory")
#define CPA_WAIT1()  asm volatile("cp.async.wait_group 1;" ::: "memory")
#define CPA_WAIT0()  asm volatile("cp.async.wait_group 0;" ::: "memory")

__device__ __forceinline__ void ldm4(uint32_t* r, uint32_t a) {
    asm volatile("ldmatrix.sync.aligned.m8n8.x4.shared.b16 {%0,%1,%2,%3}, [%4];"
        : "=r"(r[0]), "=r"(r[1]), "=r"(r[2]), "=r"(r[3]) : "r"(a));
}

__device__ __forceinline__ void mma16(float* c, const uint32_t* a, const uint32_t* b) {
    asm volatile(
        "mma.sync.aligned.m16n8k16.row.col.f32.f16.f16.f32 "
        "{%0,%1,%2,%3},{%4,%5,%6,%7},{%8,%9},{%0,%1,%2,%3};"
        : "+f"(c[0]), "+f"(c[1]), "+f"(c[2]), "+f"(c[3])
        : "r"(a[0]), "r"(a[1]), "r"(a[2]), "r"(a[3]), "r"(b[0]), "r"(b[1]));
}

// epilogue helper shared by both GEMM flavors
template<int EPI>
__device__ __forceinline__ void epi_store(
    float v0, float v1, size_t o, int n,
    const float* bias, void* Cout,
    const __half* q16, __half* mat16, __half* qm16)
{
    if (EPI == 1) {
        __half2 q2 = *(const __half2*)(q16 + o);
        float t0 = __half2float(__low2half(q2)) - v0;
        float t1 = __half2float(__high2half(q2)) - v1;
        *(__half2*)((__half*)Cout + o) = __floats2half2_rn(t0 * t0, t1 * t1);
    } else if (EPI == 2) {
        float2 w = {v0, v1};
        *(float2*)((float*)Cout + o) = w;
    } else if (EPI == 3) {
        float2 w = {v0 + __ldg(bias + n), v1 + __ldg(bias + n + 1)};
        *(float2*)((float*)Cout + o) = w;
    } else if (EPI == 4) {
        *(__half2*)((__half*)Cout + o) =
            __floats2half2_rn(tanhf(v0 + __ldg(bias + n)),
                              tanhf(v1 + __ldg(bias + n + 1)));
    } else {
        __half2 old2 = *(__half2*)(mat16 + o);
        __half2 q2 = *(const __half2*)(q16 + o);
        float n0v = fminf(1.0f, fmaxf(-1.0f,
            tanhf(v0 + __ldg(bias + n)) + __half2float(__low2half(old2))));
        float n1v = fminf(1.0f, fmaxf(-1.0f,
            tanhf(v1 + __ldg(bias + n + 1)) + __half2float(__high2half(old2))));
        *(__half2*)(mat16 + o) = __floats2half2_rn(n0v, n1v);
        *(__half2*)(qm16 + o) = __floats2half2_rn(
            __half2float(__low2half(q2)) * n0v,
            __half2float(__high2half(q2)) * n1v);
    }
}

// ================= 128N GEMM (for W1, N=640) =================
#define STAGE_BYTES 32768
#define SMEM_BYTES  (3 * STAGE_BYTES)
template<int EPI>
__global__ void __launch_bounds__(256, 2) hgemm(
    const __half* __restrict__ A, const __half* __restrict__ Bw,
    const float* __restrict__ bias, void* __restrict__ Cout,
    const __half* __restrict__ q16, __half* __restrict__ mat16,
    __half* __restrict__ qm16,
    int K, int lda, int ldc, size_t sA, size_t sB, size_t sC)
{
    extern __shared__ __half smemh[];
    const uint32_t sbase = smem_u32(smemh);

    const int tid = threadIdx.x;
    const int lane = tid & 31, warp = tid >> 5;
    const int wm = (warp & 3) * 32, wn = (warp >> 2) * 64;
    const int z = blockIdx.z;
    const int m0 = blockIdx.y * 128, n0 = blockIdx.x * 128;

    const __half* Ab = A + (size_t)z * sA;
    const __half* Bp = Bw + (size_t)z * sB;

    const int ar = tid & 127, acb = (tid >> 7) * 4;
    const int NCH = K >> 6;

    float acc[2][8][4];
#pragma unroll
    for (int i = 0; i < 2; i++)
#pragma unroll
        for (int j = 0; j < 8; j++)
#pragma unroll
            for (int r = 0; r < 4; r++) acc[i][j][r] = 0.0f;

    auto load_chunk = [&](int stage, int ch) {
        const uint32_t Abase = sbase + stage * STAGE_BYTES;
        const uint32_t Bbase = Abase + 16384;
        const __half* ga = Ab + (size_t)(m0 + ar) * lda + ch * 64 + acb * 8;
        const __half* gb = Bp + (size_t)(n0 + ar) * K + ch * 64 + acb * 8;
#pragma unroll
        for (int j = 0; j < 4; j++) {
            int c = acb + j;
            uint32_t sw = ((uint32_t)(c ^ (ar & 7))) << 4;
            cpa16(Abase + ar * 128 + sw, ga + j * 8);
            cpa16(Bbase + ar * 128 + sw, gb + j * 8);
        }
    };

    auto compute = [&](int stage) {
        const uint32_t Abase = sbase + stage * STAGE_BYTES;
        const uint32_t Bbase = Abase + 16384;
#pragma unroll
        for (int s16 = 0; s16 < 4; s16++) {
            uint32_t a[2][4];
#pragma unroll
            for (int mi = 0; mi < 2; mi++) {
                int row = wm + mi * 16 + (lane & 15);
                int c = s16 * 2 + (lane >> 4);
                ldm4(a[mi], Abase + row * 128 + (((uint32_t)(c ^ (row & 7))) << 4));
            }
            uint32_t bf[4][4];
#pragma unroll
            for (int nb = 0; nb < 4; nb++) {
                int row = wn + nb * 16 + (lane & 15);
                int c = s16 * 2 + (lane >> 4);
                ldm4(bf[nb], Bbase + row * 128 + (((uint32_t)(c ^ (row & 7))) << 4));
            }
#pragma unroll
            for (int mi = 0; mi < 2; mi++)
#pragma unroll
                for (int nb = 0; nb < 4; nb++) {
                    uint32_t b0[2] = {bf[nb][0], bf[nb][2]};
                    uint32_t b1[2] = {bf[nb][1], bf[nb][3]};
                    mma16(acc[mi][2 * nb], a[mi], b0);
                    mma16(acc[mi][2 * nb + 1], a[mi], b1);
                }
        }
    };

    load_chunk(0, 0);
    CPA_COMMIT();
    if (NCH > 1) { load_chunk(1, 1); CPA_COMMIT(); }

    for (int i = 0; i < NCH; i++) {
        if (i + 2 < NCH) { CPA_WAIT1(); } else { CPA_WAIT0(); }
        __syncthreads();
        if (i + 2 < NCH) {
            load_chunk((i + 2) % 3, i + 2);
            CPA_COMMIT();
        }
        compute(i % 3);
    }

    const int g = lane >> 2, tg = lane & 3;
#pragma unroll
    for (int mi = 0; mi < 2; mi++) {
#pragma unroll
        for (int ni = 0; ni < 8; ni++) {
            int n = n0 + wn + ni * 8 + 2 * tg;
#pragma unroll
            for (int hh = 0; hh < 2; hh++) {
                int m = m0 + wm + mi * 16 + g + hh * 8;
                size_t o = (size_t)z * sC + (size_t)m * ldc + n;
                epi_store<EPI>(acc[mi][ni][hh * 2], acc[mi][ni][hh * 2 + 1],
                               o, n, bias, Cout, q16, mat16, qm16);
            }
        }
    }
}

// ================= 256N GEMM (wc / cw / mw2) =================
// Tile 128(M) x 256(N), 256 thr, 8 warps (2M x 4N), warp tile 64x64.
#define BSTAGE_BYTES 49152
#define BSMEM_BYTES  (3 * BSTAGE_BYTES)
template<int EPI>
__global__ void __launch_bounds__(256, 1) hgemmB(
    const __half* __restrict__ A, const __half* __restrict__ Bw,
    const float* __restrict__ bias, void* __restrict__ Cout,
    const __half* __restrict__ q16, __half* __restrict__ mat16,
    __half* __restrict__ qm16,
    int K, int lda, int ldc, size_t sA, size_t sB, size_t sC)
{
    extern __shared__ __half smemh[];
    const uint32_t sbase = smem_u32(smemh);

    const int tid = threadIdx.x;
    const int lane = tid & 31, warp = tid >> 5;
    const int wm = (warp & 1) * 64, wn = (warp >> 1) * 64;
    const int z = blockIdx.z;
    const int m0 = blockIdx.y * 128, n0 = blockIdx.x * 256;

    const __half* Ab = A + (size_t)z * sA;
    const __half* Bp = Bw + (size_t)z * sB;

    const int ar = tid & 127, acb = (tid >> 7) * 4;   // A loader: 2 thr/row
    const int br = tid;                               // B loader: 1 thr/row
    const int NCH = K >> 6;

    float acc[4][8][4];
#pragma unroll
    for (int i = 0; i < 4; i++)
#pragma unroll
        for (int j = 0; j < 8; j++)
#pragma unroll
            for (int r = 0; r < 4; r++) acc[i][j][r] = 0.0f;

    auto load_chunk = [&](int stage, int ch) {
        const uint32_t Abase = sbase + stage * BSTAGE_BYTES;
        const uint32_t Bbase = Abase + 16384;
        const __half* ga = Ab + (size_t)(m0 + ar) * lda + ch * 64 + acb * 8;
#pragma unroll
        for (int j = 0; j < 4; j++) {
            int c = acb + j;
            cpa16(Abase + ar * 128 + (((uint32_t)(c ^ (ar & 7))) << 4), ga + j * 8);
        }
        const __half* gb = Bp + (size_t)(n0 + br) * K + ch * 64;
#pragma unroll
        for (int c = 0; c < 8; c++) {
            cpa16(Bbase + br * 128 + (((uint32_t)(c ^ (br & 7))) << 4), gb + c * 8);
        }
    };

    auto compute = [&](int stage) {
        const uint32_t Abase = sbase + stage * BSTAGE_BYTES;
        const uint32_t Bbase = Abase + 16384;
#pragma unroll
        for (int s16 = 0; s16 < 4; s16++) {
            const int c = s16 * 2 + (lane >> 4);
            uint32_t a[4][4];
#pragma unroll
            for (int mi = 0; mi < 4; mi++) {
                int row = wm + mi * 16 + (lane & 15);
                ldm4(a[mi], Abase + row * 128 + (((uint32_t)(c ^ (row & 7))) << 4));
            }
            uint32_t bf[4][4];
#pragma unroll
            for (int nb = 0; nb < 4; nb++) {
                int row = wn + nb * 16 + (lane & 15);
                ldm4(bf[nb], Bbase + row * 128 + (((uint32_t)(c ^ (row & 7))) << 4));
            }
#pragma unroll
            for (int mi = 0; mi < 4; mi++)
#pragma unroll
                for (int nb = 0; nb < 4; nb++) {
                    uint32_t b0[2] = {bf[nb][0], bf[nb][2]};
                    uint32_t b1[2] = {bf[nb][1], bf[nb][3]};
                    mma16(acc[mi][2 * nb], a[mi], b0);
                    mma16(acc[mi][2 * nb + 1], a[mi], b1);
                }
        }
    };

    load_chunk(0, 0);
    CPA_COMMIT();
    if (NCH > 1) { load_chunk(1, 1); CPA_COMMIT(); }

    for (int i = 0; i < NCH; i++) {
        if (i + 2 < NCH) { CPA_WAIT1(); } else { CPA_WAIT0(); }
        __syncthreads();
        if (i + 2 < NCH) {
            load_chunk((i + 2) % 3, i + 2);
            CPA_COMMIT();
        }
        compute(i % 3);
    }

    const int g = lane >> 2, tg = lane & 3;
#pragma unroll
    for (int mi = 0; mi < 4; mi++) {
#pragma unroll
        for (int ni = 0; ni < 8; ni++) {
            int n = n0 + wn + ni * 8 + 2 * tg;
#pragma unroll
            for (int hh = 0; hh < 2; hh++) {
                int m = m0 + wm + mi * 16 + g + hh * 8;
                size_t o = (size_t)z * sC + (size_t)m * ldc + n;
                epi_store<EPI>(acc[mi][ni][hh * 2], acc[mi][ni][hh * 2 + 1],
                               o, n, bias, Cout, q16, mat16, qm16);
            }
        }
    }
}

// ---------------- fused attention scan ----------------
#define AT_STAGE   49152
#define AT_SMSTR   257
#define AT_SMEM    (3 * AT_STAGE)
__global__ void __launch_bounds__(512, 1) attn_fused(
    const __half* __restrict__ ctx16, const __half* __restrict__ qm16,
    const float* __restrict__ smooth,
    __half* __restrict__ a16, float* __restrict__ a32)
{
    extern __shared__ __half smemh[];
    const uint32_t sbase = smem_u32(smemh);
    float* smf = (float*)smemh;
    float* sinv = smf + NC * AT_SMSTR;

    const int tid = threadIdx.x;
    const int lane = tid & 31, warp = tid >> 5;
    const int wm = (warp & 3) * 32, wn = (warp >> 2) * 64;
    const int b = blockIdx.x;

    const __half* Ab = ctx16 + (size_t)b * NC * D;
    const __half* Bp = qm16 + (size_t)b * NQ * D;

    const int arow = tid >> 2, ac0 = (tid & 3) * 2;
    const int brow = tid >> 1, bc0 = (tid & 1) * 4;

    float acc[2][8][4];
#pragma unroll
    for (int i = 0; i < 2; i++)
#pragma unroll
        for (int j = 0; j < 8; j++)
#pragma unroll
            for (int r = 0; r < 4; r++) acc[i][j][r] = 0.0f;

    auto load_chunk = [&](int stage, int ch) {
        const uint32_t Abase = sbase + stage * AT_STAGE;
        const uint32_t Bbase = Abase + 16384;
        const __half* ga = Ab + (size_t)arow * D + ch * 64 + ac0 * 8;
#pragma unroll
        for (int j = 0; j < 2; j++) {
            int c = ac0 + j;
            cpa16(Abase + arow * 128 + (((uint32_t)(c ^ (arow & 7))) << 4), ga + j * 8);
        }
        const __half* gb = Bp + (size_t)brow * D + ch * 64 + bc0 * 8;
#pragma unroll
        for (int j = 0; j < 4; j++) {
            int c = bc0 + j;
            cpa16(Bbase + brow * 128 + (((uint32_t)(c ^ (brow & 7))) << 4), gb + j * 8);
        }
    };

    auto compute = [&](int stage) {
        const uint32_t Abase = sbase + stage * AT_STAGE;
        const uint32_t Bbase = Abase + 16384;
#pragma unroll
        for (int s16 = 0; s16 < 4; s16++) {
            uint32_t a[2][4];
#pragma unroll
            for (int mi = 0; mi < 2; mi++) {
                int row = wm + mi * 16 + (lane & 15);
                int c = s16 * 2 + (lane >> 4);
                ldm4(a[mi], Abase + row * 128 + (((uint32_t)(c ^ (row & 7))) << 4));
            }
            uint32_t bf[4][4];
#pragma unroll
            for (int nb = 0; nb < 4; nb++) {
                int row = wn + nb * 16 + (lane & 15);
                int c = s16 * 2 + (lane >> 4);
                ldm4(bf[nb], Bbase + row * 128 + (((uint32_t)(c ^ (row & 7))) << 4));
            }
#pragma unroll
            for (int mi = 0; mi < 2; mi++)
#pragma unroll
                for (int nb = 0; nb < 4; nb++) {
                    uint32_t b0[2] = {bf[nb][0], bf[nb][2]};
                    uint32_t b1[2] = {bf[nb][1], bf[nb][3]};
                    mma16(acc[mi][2 * nb], a[mi], b0);
                    mma16(acc[mi][2 * nb + 1], a[mi], b1);
                }
        }
    };

    const int NCH = D >> 6;
    load_chunk(0, 0);
    CPA_COMMIT();
    load_chunk(1, 1);
    CPA_COMMIT();
    for (int i = 0; i < NCH; i++) {
        if (i + 2 < NCH) { CPA_WAIT1(); } else { CPA_WAIT0(); }
        __syncthreads();
        if (i + 2 < NCH) {
            load_chunk((i + 2) % 3, i + 2);
            CPA_COMMIT();
        }
        compute(i % 3);
    }

    __syncthreads();
    const int g = lane >> 2, tg = lane & 3;
#pragma unroll
    for (int mi = 0; mi < 2; mi++) {
#pragma unroll
        for (int ni = 0; ni < 8; ni++) {
            int n = wn + ni * 8 + 2 * tg;
#pragma unroll
            for (int hh = 0; hh < 2; hh++) {
                int m = wm + mi * 16 + g + hh * 8;
                float v0 = acc[mi][ni][hh * 2 + 0];
                float v1 = acc[mi][ni][hh * 2 + 1];
                smf[m * AT_SMSTR + n]     = (v0 >= 0.0f) ? v0 : 0.1f * v0;
                smf[m * AT_SMSTR + n + 1] = (v1 >= 0.0f) ? v1 : 0.1f * v1;
            }
        }
    }
    __syncthreads();

#pragma unroll
    for (int r = 0; r < 8; r++) {
        int c = warp * 8 + r;
        const float* p = smf + c * AT_SMSTR;
        float s = 0.0f;
#pragma unroll
        for (int j = 0; j < 8; j++) {
            float x = p[lane + 32 * j];
            s += x * x;
        }
        s = warp_sum(s);
        if (lane == 0) sinv[c] = 1.0f / (sqrtf(s) + 1e-8f);
    }
    __syncthreads();

    for (int qi = warp; qi < NQ; qi += 16) {
        float sf = smooth[b * NQ + qi];
        float v0 = smf[(lane)      * AT_SMSTR + qi] * sinv[lane]      * sf;
        float v1 = smf[(lane + 32) * AT_SMSTR + qi] * sinv[lane + 32] * sf;
        float v2 = smf[(lane + 64) * AT_SMSTR + qi] * sinv[lane + 64] * sf;
        float v3 = smf[(lane + 96) * AT_SMSTR + qi] * sinv[lane + 96] * sf;
        float mx = fmaxf(fmaxf(v0, v1), fmaxf(v2, v3));
#pragma unroll
        for (int o = 16; o > 0; o >>= 1) mx = fmaxf(mx, __shfl_xor_sync(0xffffffffu, mx, o));
        float e0 = expf(v0 - mx), e1 = expf(v1 - mx), e2 = expf(v2 - mx), e3 = expf(v3 - mx);
        float s = warp_sum(e0 + e1 + e2 + e3);
        float inv = 1.0f / s;
        size_t base = ((size_t)b * NQ + qi) * NC;
        a16[base + lane]      = __float2half_rn(e0 * inv);
        a16[base + lane + 32] = __float2half_rn(e1 * inv);
        a16[base + lane + 64] = __float2half_rn(e2 * inv);
        a16[base + lane + 96] = __float2half_rn(e3 * inv);
        if (a32) {
            a32[base + lane]      = e0 * inv;
            a32[base + lane + 32] = e1 * inv;
            a32[base + lane + 64] = e2 * inv;
            a32[base + lane + 96] = e3 * inv;
        }
    }
}

// ---------------- transposes ----------------
__device__ __forceinline__ void tr_tile(const float* s, __half* d, int R, int C,
                                        int bx, int by) {
    __shared__ float t[32][33];
    int r0 = by * 32, c0 = bx * 32;
    for (int j = threadIdx.y; j < 32; j += 8)
        t[j][threadIdx.x] = s[(size_t)(r0 + j) * C + c0 + threadIdx.x];
    __syncthreads();
    for (int j = threadIdx.y; j < 32; j += 8)
        d[(size_t)(c0 + j) * R + r0 + threadIdx.x] = __float2half_rn(t[threadIdx.x][j]);
}

__global__ void transpose_ctx(const float* __restrict__ ctx, __half* __restrict__ dst) {
    const float* s = ctx + (size_t)blockIdx.z * NC * D;
    __half* d = dst + (size_t)blockIdx.z * NC * D;
    tr_tile(s, d, NC, D, blockIdx.x, blockIdx.y);
}

__global__ void transpose_weights(const float* __restrict__ cw, const float* __restrict__ sw1,
                                  const float* __restrict__ mw1, const float* __restrict__ mw2,
                                  __half* __restrict__ w16) {
    int blk = blockIdx.x;
    const float* src; __half* dst; int R, C;
    if (blk < 512) {
        int l = blk >> 8; blk &= 255;
        src = cw + (size_t)l * D * AD; dst = w16 + W_CW + (size_t)l * AD * D;
        R = D; C = AD;
    } else if (blk < 576) {
        blk -= 512; int l = blk >> 5; blk &= 31;
        src = sw1 + (size_t)l * AD * HD; dst = w16 + W_W1 + (size_t)l * W1N * AD + 512 * AD;
        R = AD; C = HD;
    } else if (blk < 832) {
        blk -= 576; int l = blk >> 7; blk &= 127;
        src = mw1 + (size_t)l * AD * MD; dst = w16 + W_W1 + (size_t)l * W1N * AD;
        R = AD; C = MD;
    } else {
        blk -= 832; int l = blk >> 9; blk &= 511;
        src = mw2 + (size_t)l * MD * D; dst = w16 + W_W2 + (size_t)l * D * MD;
        R = MD; C = D;
    }
    int bx = blk % (C / 32), by = blk / (C / 32);
    tr_tile(src, dst, R, C, bx, by);
}

__global__ void pack_bias(const float* __restrict__ mw_b1, const float* __restrict__ sw_b1,
                          float* __restrict__ pb) {
    int i = blockIdx.x * blockDim.x + threadIdx.x;
    if (i < 2 * W1N) {
        int l = i / W1N, n = i % W1N;
        pb[i] = (n < MD) ? mw_b1[l * MD + n] : sw_b1[l * HD + n - MD];
    }
}

// ---------------- elementwise kernels ----------------
__global__ void init_kernel(const float* __restrict__ query,
                            __half* __restrict__ mat16, float* __restrict__ smooth,
                            __half* __restrict__ q16, __half* __restrict__ qm16) {
    size_t i = ((size_t)blockIdx.x * blockDim.x + threadIdx.x) * 4;
    if (i < (size_t)Bb * NQ * D) {
        float4 q = *(const float4*)(query + i);
        __half2 h0 = __floats2half2_rn(q.x, q.y);
        __half2 h1 = __floats2half2_rn(q.z, q.w);
        __half2 one2 = __floats2half2_rn(1.0f, 1.0f);
        *(__half2*)(q16 + i)      = h0;
        *(__half2*)(q16 + i + 2)  = h1;
        *(__half2*)(qm16 + i)     = h0;
        *(__half2*)(qm16 + i + 2) = h1;
        *(__half2*)(mat16 + i)     = one2;
        *(__half2*)(mat16 + i + 2) = one2;
    }
    if (i < (size_t)Bb * NQ * 4) smooth[i / 4] = 10.0f;
}

__global__ void convert_kernel(const float* __restrict__ src, __half* __restrict__ dst, int n) {
    int i = (blockIdx.x * blockDim.x + threadIdx.x) * 4;
    if (i < n) {
        float4 v = *(const float4*)(src + i);
        *(__half2*)(dst + i)     = __floats2half2_rn(v.x, v.y);
        *(__half2*)(dst + i + 2) = __floats2half2_rn(v.z, v.w);
    }
}

__global__ void l2norm256_kernel(const float* __restrict__ X, __half* __restrict__ Y) {
    int row = blockIdx.x * 8 + (threadIdx.x >> 5);
    int lane = threadIdx.x & 31;
    const float* p = X + (size_t)row * AD;
    float vals[8];
    float s = 0.0f;
#pragma unroll
    for (int j = 0; j < 8; j++) {
        vals[j] = p[lane + 32 * j];
        s += vals[j] * vals[j];
    }
    s = warp_sum(s);
    float inv = 1.0f / (sqrtf(s) + 1e-8f);
    __half* y = Y + (size_t)row * AD;
#pragma unroll
    for (int j = 0; j < 8; j++)
        y[lane + 32 * j] = __float2half_rn(vals[j] * inv);
}

__global__ void sw_reduce_kernel(const __half* __restrict__ hs, const float* __restrict__ w2,
                                 const float* __restrict__ b2, float* __restrict__ smooth)
{
    int row = blockIdx.x * 8 + (threadIdx.x >> 5);
    int lane = threadIdx.x & 31;
    const __half* r = hs + (size_t)row * W1N + MD;
    float s = __half2float(r[lane]) * w2[lane]
            + __half2float(r[lane + 32]) * w2[lane + 32]
            + __half2float(r[lane + 64]) * w2[lane + 64]
            + __half2float(r[lane + 96]) * w2[lane + 96];
    s = warp_sum(s);
    if (lane == 0) smooth[row] = fmaxf(0.0f, s + b2[0] + smooth[row]);
}

// ---------------- orchestration ----------------
extern "C" void kernel_launch(void* const* d_in, const int* in_sizes, int n_in,
                              void* d_out, int out_size)
{
    const float* query = (const float*)d_in[0];
    const float* ctx   = (const float*)d_in[1];
    const float* cw_W  = (const float*)d_in[2];
    const float* cw_b  = (const float*)d_in[3];
    const float* sw_W1 = (const float*)d_in[4];
    const float* sw_b1 = (const float*)d_in[5];
    const float* sw_W2 = (const float*)d_in[6];
    const float* sw_b2 = (const float*)d_in[7];
    const float* mw_W1 = (const float*)d_in[8];
    const float* mw_b1 = (const float*)d_in[9];
    const float* mw_W2 = (const float*)d_in[10];
    const float* mw_b2 = (const float*)d_in[11];

    float* out      = (float*)d_out;
    float* out_q    = out;
    float* out_wc   = out + (size_t)Bb * NQ * D;
    float* out_attn = out + 2 * (size_t)Bb * NQ * D;

    float *psm, *pcom, *ppb;
    __half *pmat, *pq16, *pqm, *pctx16, *pctxT, *pattn16, *pd16, *pcom16, *phs16, *pw16;
    cudaGetSymbolAddress((void**)&psm,     g_smooth);
    cudaGetSymbolAddress((void**)&pcom,    g_common);
    cudaGetSymbolAddress((void**)&ppb,     g_pb);
    cudaGetSymbolAddress((void**)&pmat,    g_mat16);
    cudaGetSymbolAddress((void**)&pq16,    g_q16);
    cudaGetSymbolAddress((void**)&pqm,     g_qm16);
    cudaGetSymbolAddress((void**)&pctx16,  g_ctx16);
    cudaGetSymbolAddress((void**)&pctxT,   g_ctxT16);
    cudaGetSymbolAddress((void**)&pattn16, g_attn16);
    cudaGetSymbolAddress((void**)&pd16,    g_d16);
    cudaGetSymbolAddress((void**)&pcom16,  g_com16);
    cudaGetSymbolAddress((void**)&phs16,   g_hs16);
    cudaGetSymbolAddress((void**)&pw16,    g_w16);

    cudaFuncSetAttribute(hgemm<4>,  cudaFuncAttributeMaxDynamicSharedMemorySize, SMEM_BYTES);
    cudaFuncSetAttribute(hgemmB<1>, cudaFuncAttributeMaxDynamicSharedMemorySize, BSMEM_BYTES);
    cudaFuncSetAttribute(hgemmB<2>, cudaFuncAttributeMaxDynamicSharedMemorySize, BSMEM_BYTES);
    cudaFuncSetAttribute(hgemmB<3>, cudaFuncAttributeMaxDynamicSharedMemorySize, BSMEM_BYTES);
    cudaFuncSetAttribute(hgemmB<5>, cudaFuncAttributeMaxDynamicSharedMemorySize, BSMEM_BYTES);
    cudaFuncSetAttribute(attn_fused, cudaFuncAttributeMaxDynamicSharedMemorySize, AT_SMEM);

    // prep; attn_fused placed at launch #3 so ncu's capture slot shows the GEMM
    init_kernel<<<(Bb * NQ * D / 4 + 255) / 256, 256>>>(query, pmat, psm, pq16, pqm);
    convert_kernel<<<(Bb * NC * D / 4 + 255) / 256, 256>>>(ctx, pctx16, Bb * NC * D);
    transpose_ctx<<<dim3(D / 32, NC / 32, Bb), dim3(32, 8)>>>(ctx, pctxT);
    attn_fused<<<Bb, 512, AT_SMEM>>>(pctx16, pqm, psm, pattn16, nullptr);   // scan, iter 0
    transpose_weights<<<1856, dim3(32, 8)>>>(cw_W, sw_W1, mw_W1, mw_W2, pw16);
    pack_bias<<<(2 * W1N + 255) / 256, 256>>>(mw_b1, sw_b1, ppb);

    for (int i = 0; i < 2; i++) {
        // d16 = (q - attn@ctx)^2   (M=256/128=2, N=1024/256=4, batch)
        hgemmB<1><<<dim3(4, 2, Bb), 256, BSMEM_BYTES>>>(
            pattn16, pctxT, nullptr, pd16, pq16, nullptr, nullptr,
            NC, NC, D, (size_t)NQ * NC, (size_t)NC * D, (size_t)NQ * D);
        // common = d16 @ cw_W + b  (M=32768/128=256, N=256/256=1)
        hgemmB<3><<<dim3(1, 256, 1), 256, BSMEM_BYTES>>>(
            pd16, pw16 + W_CW + (size_t)i * AD * D, cw_b + (size_t)i * AD, pcom,
            nullptr, nullptr, nullptr, D, D, AD, 0, 0, 0);
        l2norm256_kernel<<<Bb * NQ / 8, 256>>>(pcom, pcom16);
        // fused W1 (N=640, keep 128N kernel)
        hgemm<4><<<dim3(5, 256, 1), 256, SMEM_BYTES>>>(
            pcom16, pw16 + W_W1 + (size_t)i * W1N * AD, ppb + (size_t)i * W1N, phs16,
            nullptr, nullptr, nullptr, AD, AD, W1N, 0, 0, 0);
        sw_reduce_kernel<<<Bb * NQ / 8, 256>>>(phs16, sw_W2 + (size_t)i * HD, sw_b2 + i, psm);
        // matrix update  (M=256, N=1024/256=4)
        hgemmB<5><<<dim3(4, 256, 1), 256, BSMEM_BYTES>>>(
            phs16, pw16 + W_W2 + (size_t)i * D * MD, mw_b2 + (size_t)i * D, nullptr,
            pq16, pmat, pqm, MD, W1N, D, 0, 0, 0);
        // next scan (iter i+1 or final)
        attn_fused<<<Bb, 512, AT_SMEM>>>(pctx16, pqm, psm, pattn16,
                                         (i == 1) ? out_attn : nullptr);
    }

    // final wc -> d_out
    hgemmB<2><<<dim3(4, 2, Bb), 256, BSMEM_BYTES>>>(
        pattn16, pctxT, nullptr, out_wc, nullptr, nullptr, nullptr,
        NC, NC, D, (size_t)NQ * NC, (size_t)NC * D, (size_t)NQ * D);

    cudaMemcpyAsync(out_q, query, (size_t)Bb * NQ * D * sizeof(float),
                    cudaMemcpyDeviceToDevice, 0);
}

// round 12
// speedup vs baseline: 1.0439x; 1.0439x over previous
#include <cuda_runtime.h>
#include <cuda_fp16.h>
#include <stdint.h>
#include <math.h>

// Problem constants
#define Bb 128
#define NQ 256
#define NC 128
#define D  1024
#define AD 256
#define HD 128
#define MD 512
#define W1N 640   // MD + HD fused N

// packed transposed weight offsets (halves)
#define W_CW  0
#define W_W1  (W_CW + 2 * AD * D)
#define W_W2  (W_W1 + 2 * W1N * AD)
#define W_TOT (W_W2 + 2 * D * MD)

// ---------------- scratch (device globals) ----------------
__device__ float  g_smooth[Bb * NQ];
__device__ float  g_common[Bb * NQ * AD];
__device__ float  g_pb[2 * W1N];
__device__ __half g_mat16[Bb * NQ * D];
__device__ __half g_q16[Bb * NQ * D];
__device__ __half g_qm16[Bb * NQ * D];
__device__ __half g_ctx16[Bb * NC * D];
__device__ __half g_ctxT16[Bb * D * NC];
__device__ __half g_attn16[Bb * NQ * NC];
__device__ __half g_d16[Bb * NQ * D];
__device__ __half g_com16[Bb * NQ * AD];
__device__ __half g_hs16[Bb * NQ * W1N];
__device__ __half g_w16[W_TOT];

// ---------------- utils ----------------
__device__ __forceinline__ float warp_sum(float v) {
#pragma unroll
    for (int o = 16; o > 0; o >>= 1) v += __shfl_xor_sync(0xffffffffu, v, o);
    return v;
}

__device__ __forceinline__ uint32_t smem_u32(const void* p) {
    uint32_t a;
    asm("{ .reg .u64 t; cvta.to.shared.u64 t, %1; cvt.u32.u64 %0, t; }" : "=r"(a) : "l"(p));
    return a;
}

__device__ __forceinline__ void cpa16(uint32_t dst, const void* src) {
    asm volatile("cp.async.cg.shared.global [%0], [%1], 16;" :: "r"(dst), "l"(src));
}
#define CPA_COMMIT() asm volatile("cp.async.commit_group;" ::: "memory")
#define CPA_WAIT1()  asm volatile("cp.async.wait_group 1;" ::: "memory")
#define CPA_WAIT0()  asm volatile("cp.async.wait_group 0;" ::: "memory")

__device__ __forceinline__ void ldm4(uint32_t* r, uint32_t a) {
    asm volatile("ldmatrix.sync.aligned.m8n8.x4.shared.b16 {%0,%1,%2,%3}, [%4];"
        : "=r"(r[0]), "=r"(r[1]), "=r"(r[2]), "=r"(r[3]) : "r"(a));
}

__device__ __forceinline__ void mma16(float* c, const uint32_t* a, const uint32_t* b) {
    asm volatile(
        "mma.sync.aligned.m16n8k16.row.col.f32.f16.f16.f32 "
        "{%0,%1,%2,%3},{%4,%5,%6,%7},{%8,%9},{%0,%1,%2,%3};"
        : "+f"(c[0]), "+f"(c[1]), "+f"(c[2]), "+f"(c[3])
        : "r"(a[0]), "r"(a[1]), "r"(a[2]), "r"(a[3]), "r"(b[0]), "r"(b[1]));
}

// epilogue helper
template<int EPI>
__device__ __forceinline__ void epi_store(
    float v0, float v1, size_t o, int n,
    const float* bias, void* Cout,
    const __half* q16, __half* mat16, __half* qm16)
{
    if (EPI == 1) {
        __half2 q2 = *(const __half2*)(q16 + o);
        float t0 = __half2float(__low2half(q2)) - v0;
        float t1 = __half2float(__high2half(q2)) - v1;
        *(__half2*)((__half*)Cout + o) = __floats2half2_rn(t0 * t0, t1 * t1);
    } else if (EPI == 2) {
        float2 w = {v0, v1};
        *(float2*)((float*)Cout + o) = w;
    } else if (EPI == 3) {
        float2 w = {v0 + __ldg(bias + n), v1 + __ldg(bias + n + 1)};
        *(float2*)((float*)Cout + o) = w;
    } else if (EPI == 4) {
        *(__half2*)((__half*)Cout + o) =
            __floats2half2_rn(tanhf(v0 + __ldg(bias + n)),
                              tanhf(v1 + __ldg(bias + n + 1)));
    } else {
        __half2 old2 = *(__half2*)(mat16 + o);
        __half2 q2 = *(const __half2*)(q16 + o);
        float n0v = fminf(1.0f, fmaxf(-1.0f,
            tanhf(v0 + __ldg(bias + n)) + __half2float(__low2half(old2))));
        float n1v = fminf(1.0f, fmaxf(-1.0f,
            tanhf(v1 + __ldg(bias + n + 1)) + __half2float(__high2half(old2))));
        *(__half2*)(mat16 + o) = __floats2half2_rn(n0v, n1v);
        *(__half2*)(qm16 + o) = __floats2half2_rn(
            __half2float(__low2half(q2)) * n0v,
            __half2float(__high2half(q2)) * n1v);
    }
}

// ================= GEMM: 128x128 tile, 512 thr, warp tile 32x32, 2 CTA/SM ======
#define STAGE_BYTES 32768
#define SMEM_BYTES  (3 * STAGE_BYTES)
template<int EPI>
__global__ void __launch_bounds__(512, 2) hgemm(
    const __half* __restrict__ A, const __half* __restrict__ Bw,
    const float* __restrict__ bias, void* __restrict__ Cout,
    const __half* __restrict__ q16, __half* __restrict__ mat16,
    __half* __restrict__ qm16,
    int K, int lda, int ldc, size_t sA, size_t sB, size_t sC)
{
    extern __shared__ __half smemh[];
    const uint32_t sbase = smem_u32(smemh);

    const int tid = threadIdx.x;
    const int lane = tid & 31, warp = tid >> 5;
    const int wm = (warp & 3) * 32, wn = (warp >> 2) * 32;   // 4M x 4N warps
    const int z = blockIdx.z;
    const int m0 = blockIdx.y * 128, n0 = blockIdx.x * 128;

    const __half* Ab = A + (size_t)z * sA;
    const __half* Bp = Bw + (size_t)z * sB;

    const int ar = tid & 127, ac = tid >> 7;   // row 0..127, col base 0..3
    const int NCH = K >> 6;

    float acc[2][4][4];
#pragma unroll
    for (int i = 0; i < 2; i++)
#pragma unroll
        for (int j = 0; j < 4; j++)
#pragma unroll
            for (int r = 0; r < 4; r++) acc[i][j][r] = 0.0f;

    auto load_chunk = [&](int stage, int ch) {
        const uint32_t Abase = sbase + stage * STAGE_BYTES;
        const uint32_t Bbase = Abase + 16384;
        const __half* ga = Ab + (size_t)(m0 + ar) * lda + ch * 64;
        const __half* gb = Bp + (size_t)(n0 + ar) * K + ch * 64;
#pragma unroll
        for (int j = 0; j < 2; j++) {
            int c = ac + j * 4;
            uint32_t sw = ((uint32_t)(c ^ (ar & 7))) << 4;
            cpa16(Abase + ar * 128 + sw, ga + c * 8);
            cpa16(Bbase + ar * 128 + sw, gb + c * 8);
        }
    };

    auto compute = [&](int stage) {
        const uint32_t Abase = sbase + stage * STAGE_BYTES;
        const uint32_t Bbase = Abase + 16384;
#pragma unroll
        for (int s16 = 0; s16 < 4; s16++) {
            const int c = s16 * 2 + (lane >> 4);
            uint32_t a[2][4];
#pragma unroll
            for (int mi = 0; mi < 2; mi++) {
                int row = wm + mi * 16 + (lane & 15);
                ldm4(a[mi], Abase + row * 128 + (((uint32_t)(c ^ (row & 7))) << 4));
            }
            uint32_t bf[2][4];
#pragma unroll
            for (int nb = 0; nb < 2; nb++) {
                int row = wn + nb * 16 + (lane & 15);
                ldm4(bf[nb], Bbase + row * 128 + (((uint32_t)(c ^ (row & 7))) << 4));
            }
#pragma unroll
            for (int mi = 0; mi < 2; mi++)
#pragma unroll
                for (int nb = 0; nb < 2; nb++) {
                    uint32_t b0[2] = {bf[nb][0], bf[nb][2]};
                    uint32_t b1[2] = {bf[nb][1], bf[nb][3]};
                    mma16(acc[mi][2 * nb], a[mi], b0);
                    mma16(acc[mi][2 * nb + 1], a[mi], b1);
                }
        }
    };

    load_chunk(0, 0);
    CPA_COMMIT();
    if (NCH > 1) { load_chunk(1, 1); CPA_COMMIT(); }

    for (int i = 0; i < NCH; i++) {
        if (i + 2 < NCH) { CPA_WAIT1(); } else { CPA_WAIT0(); }
        __syncthreads();
        if (i + 2 < NCH) {
            load_chunk((i + 2) % 3, i + 2);
            CPA_COMMIT();
        }
        compute(i % 3);
    }

    const int g = lane >> 2, tg = lane & 3;
#pragma unroll
    for (int mi = 0; mi < 2; mi++) {
#pragma unroll
        for (int ni = 0; ni < 4; ni++) {
            int n = n0 + wn + ni * 8 + 2 * tg;
#pragma unroll
            for (int hh = 0; hh < 2; hh++) {
                int m = m0 + wm + mi * 16 + g + hh * 8;
                size_t o = (size_t)z * sC + (size_t)m * ldc + n;
                epi_store<EPI>(acc[mi][ni][hh * 2], acc[mi][ni][hh * 2 + 1],
                               o, n, bias, Cout, q16, mat16, qm16);
            }
        }
    }
}

// ---------------- fused attention scan (unchanged from R10) ----------------
#define AT_STAGE   49152
#define AT_SMSTR   257
#define AT_SMEM    (3 * AT_STAGE)
__global__ void __launch_bounds__(512, 1) attn_fused(
    const __half* __restrict__ ctx16, const __half* __restrict__ qm16,
    const float* __restrict__ smooth,
    __half* __restrict__ a16, float* __restrict__ a32)
{
    extern __shared__ __half smemh[];
    const uint32_t sbase = smem_u32(smemh);
    float* smf = (float*)smemh;
    float* sinv = smf + NC * AT_SMSTR;

    const int tid = threadIdx.x;
    const int lane = tid & 31, warp = tid >> 5;
    const int wm = (warp & 3) * 32, wn = (warp >> 2) * 64;
    const int b = blockIdx.x;

    const __half* Ab = ctx16 + (size_t)b * NC * D;
    const __half* Bp = qm16 + (size_t)b * NQ * D;

    const int arow = tid >> 2, ac0 = (tid & 3) * 2;
    const int brow = tid >> 1, bc0 = (tid & 1) * 4;

    float acc[2][8][4];
#pragma unroll
    for (int i = 0; i < 2; i++)
#pragma unroll
        for (int j = 0; j < 8; j++)
#pragma unroll
            for (int r = 0; r < 4; r++) acc[i][j][r] = 0.0f;

    auto load_chunk = [&](int stage, int ch) {
        const uint32_t Abase = sbase + stage * AT_STAGE;
        const uint32_t Bbase = Abase + 16384;
        const __half* ga = Ab + (size_t)arow * D + ch * 64 + ac0 * 8;
#pragma unroll
        for (int j = 0; j < 2; j++) {
            int c = ac0 + j;
            cpa16(Abase + arow * 128 + (((uint32_t)(c ^ (arow & 7))) << 4), ga + j * 8);
        }
        const __half* gb = Bp + (size_t)brow * D + ch * 64 + bc0 * 8;
#pragma unroll
        for (int j = 0; j < 4; j++) {
            int c = bc0 + j;
            cpa16(Bbase + brow * 128 + (((uint32_t)(c ^ (brow & 7))) << 4), gb + j * 8);
        }
    };

    auto compute = [&](int stage) {
        const uint32_t Abase = sbase + stage * AT_STAGE;
        const uint32_t Bbase = Abase + 16384;
#pragma unroll
        for (int s16 = 0; s16 < 4; s16++) {
            uint32_t a[2][4];
#pragma unroll
            for (int mi = 0; mi < 2; mi++) {
                int row = wm + mi * 16 + (lane & 15);
                int c = s16 * 2 + (lane >> 4);
                ldm4(a[mi], Abase + row * 128 + (((uint32_t)(c ^ (row & 7))) << 4));
            }
            uint32_t bf[4][4];
#pragma unroll
            for (int nb = 0; nb < 4; nb++) {
                int row = wn + nb * 16 + (lane & 15);
                int c = s16 * 2 + (lane >> 4);
                ldm4(bf[nb], Bbase + row * 128 + (((uint32_t)(c ^ (row & 7))) << 4));
            }
#pragma unroll
            for (int mi = 0; mi < 2; mi++)
#pragma unroll
                for (int nb = 0; nb < 4; nb++) {
                    uint32_t b0[2] = {bf[nb][0], bf[nb][2]};
                    uint32_t b1[2] = {bf[nb][1], bf[nb][3]};
                    mma16(acc[mi][2 * nb], a[mi], b0);
                    mma16(acc[mi][2 * nb + 1], a[mi], b1);
                }
        }
    };

    const int NCH = D >> 6;
    load_chunk(0, 0);
    CPA_COMMIT();
    load_chunk(1, 1);
    CPA_COMMIT();
    for (int i = 0; i < NCH; i++) {
        if (i + 2 < NCH) { CPA_WAIT1(); } else { CPA_WAIT0(); }
        __syncthreads();
        if (i + 2 < NCH) {
            load_chunk((i + 2) % 3, i + 2);
            CPA_COMMIT();
        }
        compute(i % 3);
    }

    __syncthreads();
    const int g = lane >> 2, tg = lane & 3;
#pragma unroll
    for (int mi = 0; mi < 2; mi++) {
#pragma unroll
        for (int ni = 0; ni < 8; ni++) {
            int n = wn + ni * 8 + 2 * tg;
#pragma unroll
            for (int hh = 0; hh < 2; hh++) {
                int m = wm + mi * 16 + g + hh * 8;
                float v0 = acc[mi][ni][hh * 2 + 0];
                float v1 = acc[mi][ni][hh * 2 + 1];
                smf[m * AT_SMSTR + n]     = (v0 >= 0.0f) ? v0 : 0.1f * v0;
                smf[m * AT_SMSTR + n + 1] = (v1 >= 0.0f) ? v1 : 0.1f * v1;
            }
        }
    }
    __syncthreads();

#pragma unroll
    for (int r = 0; r < 8; r++) {
        int c = warp * 8 + r;
        const float* p = smf + c * AT_SMSTR;
        float s = 0.0f;
#pragma unroll
        for (int j = 0; j < 8; j++) {
            float x = p[lane + 32 * j];
            s += x * x;
        }
        s = warp_sum(s);
        if (lane == 0) sinv[c] = 1.0f / (sqrtf(s) + 1e-8f);
    }
    __syncthreads();

    for (int qi = warp; qi < NQ; qi += 16) {
        float sf = smooth[b * NQ + qi];
        float v0 = smf[(lane)      * AT_SMSTR + qi] * sinv[lane]      * sf;
        float v1 = smf[(lane + 32) * AT_SMSTR + qi] * sinv[lane + 32] * sf;
        float v2 = smf[(lane + 64) * AT_SMSTR + qi] * sinv[lane + 64] * sf;
        float v3 = smf[(lane + 96) * AT_SMSTR + qi] * sinv[lane + 96] * sf;
        float mx = fmaxf(fmaxf(v0, v1), fmaxf(v2, v3));
#pragma unroll
        for (int o = 16; o > 0; o >>= 1) mx = fmaxf(mx, __shfl_xor_sync(0xffffffffu, mx, o));
        float e0 = expf(v0 - mx), e1 = expf(v1 - mx), e2 = expf(v2 - mx), e3 = expf(v3 - mx);
        float s = warp_sum(e0 + e1 + e2 + e3);
        float inv = 1.0f / s;
        size_t base = ((size_t)b * NQ + qi) * NC;
        a16[base + lane]      = __float2half_rn(e0 * inv);
        a16[base + lane + 32] = __float2half_rn(e1 * inv);
        a16[base + lane + 64] = __float2half_rn(e2 * inv);
        a16[base + lane + 96] = __float2half_rn(e3 * inv);
        if (a32) {
            a32[base + lane]      = e0 * inv;
            a32[base + lane + 32] = e1 * inv;
            a32[base + lane + 64] = e2 * inv;
            a32[base + lane + 96] = e3 * inv;
        }
    }
}

// ---------------- transposes ----------------
__device__ __forceinline__ void tr_tile(const float* s, __half* d, int R, int C,
                                        int bx, int by) {
    __shared__ float t[32][33];
    int r0 = by * 32, c0 = bx * 32;
    for (int j = threadIdx.y; j < 32; j += 8)
        t[j][threadIdx.x] = s[(size_t)(r0 + j) * C + c0 + threadIdx.x];
    __syncthreads();
    for (int j = threadIdx.y; j < 32; j += 8)
        d[(size_t)(c0 + j) * R + r0 + threadIdx.x] = __float2half_rn(t[threadIdx.x][j]);
}

__global__ void transpose_ctx(const float* __restrict__ ctx, __half* __restrict__ dst) {
    const float* s = ctx + (size_t)blockIdx.z * NC * D;
    __half* d = dst + (size_t)blockIdx.z * NC * D;
    tr_tile(s, d, NC, D, blockIdx.x, blockIdx.y);
}

__global__ void transpose_weights(const float* __restrict__ cw, const float* __restrict__ sw1,
                                  const float* __restrict__ mw1, const float* __restrict__ mw2,
                                  __half* __restrict__ w16) {
    int blk = blockIdx.x;
    const float* src; __half* dst; int R, C;
    if (blk < 512) {
        int l = blk >> 8; blk &= 255;
        src = cw + (size_t)l * D * AD; dst = w16 + W_CW + (size_t)l * AD * D;
        R = D; C = AD;
    } else if (blk < 576) {
        blk -= 512; int l = blk >> 5; blk &= 31;
        src = sw1 + (size_t)l * AD * HD; dst = w16 + W_W1 + (size_t)l * W1N * AD + 512 * AD;
        R = AD; C = HD;
    } else if (blk < 832) {
        blk -= 576; int l = blk >> 7; blk &= 127;
        src = mw1 + (size_t)l * AD * MD; dst = w16 + W_W1 + (size_t)l * W1N * AD;
        R = AD; C = MD;
    } else {
        blk -= 832; int l = blk >> 9; blk &= 511;
        src = mw2 + (size_t)l * MD * D; dst = w16 + W_W2 + (size_t)l * D * MD;
        R = MD; C = D;
    }
    int bx = blk % (C / 32), by = blk / (C / 32);
    tr_tile(src, dst, R, C, bx, by);
}

__global__ void pack_bias(const float* __restrict__ mw_b1, const float* __restrict__ sw_b1,
                          float* __restrict__ pb) {
    int i = blockIdx.x * blockDim.x + threadIdx.x;
    if (i < 2 * W1N) {
        int l = i / W1N, n = i % W1N;
        pb[i] = (n < MD) ? mw_b1[l * MD + n] : sw_b1[l * HD + n - MD];
    }
}

// ---------------- elementwise kernels ----------------
__global__ void init_kernel(const float* __restrict__ query,
                            __half* __restrict__ mat16, float* __restrict__ smooth,
                            __half* __restrict__ q16, __half* __restrict__ qm16) {
    size_t i = ((size_t)blockIdx.x * blockDim.x + threadIdx.x) * 4;
    if (i < (size_t)Bb * NQ * D) {
        float4 q = *(const float4*)(query + i);
        __half2 h0 = __floats2half2_rn(q.x, q.y);
        __half2 h1 = __floats2half2_rn(q.z, q.w);
        __half2 one2 = __floats2half2_rn(1.0f, 1.0f);
        *(__half2*)(q16 + i)      = h0;
        *(__half2*)(q16 + i + 2)  = h1;
        *(__half2*)(qm16 + i)     = h0;
        *(__half2*)(qm16 + i + 2) = h1;
        *(__half2*)(mat16 + i)     = one2;
        *(__half2*)(mat16 + i + 2) = one2;
    }
    if (i < (size_t)Bb * NQ * 4) smooth[i / 4] = 10.0f;
}

__global__ void convert_kernel(const float* __restrict__ src, __half* __restrict__ dst, int n) {
    int i = (blockIdx.x * blockDim.x + threadIdx.x) * 4;
    if (i < n) {
        float4 v = *(const float4*)(src + i);
        *(__half2*)(dst + i)     = __floats2half2_rn(v.x, v.y);
        *(__half2*)(dst + i + 2) = __floats2half2_rn(v.z, v.w);
    }
}

__global__ void l2norm256_kernel(const float* __restrict__ X, __half* __restrict__ Y) {
    int row = blockIdx.x * 8 + (threadIdx.x >> 5);
    int lane = threadIdx.x & 31;
    const float* p = X + (size_t)row * AD;
    float vals[8];
    float s = 0.0f;
#pragma unroll
    for (int j = 0; j < 8; j++) {
        vals[j] = p[lane + 32 * j];
        s += vals[j] * vals[j];
    }
    s = warp_sum(s);
    float inv = 1.0f / (sqrtf(s) + 1e-8f);
    __half* y = Y + (size_t)row * AD;
#pragma unroll
    for (int j = 0; j < 8; j++)
        y[lane + 32 * j] = __float2half_rn(vals[j] * inv);
}

__global__ void sw_reduce_kernel(const __half* __restrict__ hs, const float* __restrict__ w2,
                                 const float* __restrict__ b2, float* __restrict__ smooth)
{
    int row = blockIdx.x * 8 + (threadIdx.x >> 5);
    int lane = threadIdx.x & 31;
    const __half* r = hs + (size_t)row * W1N + MD;
    float s = __half2float(r[lane]) * w2[lane]
            + __half2float(r[lane + 32]) * w2[lane + 32]
            + __half2float(r[lane + 64]) * w2[lane + 64]
            + __half2float(r[lane + 96]) * w2[lane + 96];
    s = warp_sum(s);
    if (lane == 0) smooth[row] = fmaxf(0.0f, s + b2[0] + smooth[row]);
}

// ---------------- orchestration ----------------
extern "C" void kernel_launch(void* const* d_in, const int* in_sizes, int n_in,
                              void* d_out, int out_size)
{
    const float* query = (const float*)d_in[0];
    const float* ctx   = (const float*)d_in[1];
    const float* cw_W  = (const float*)d_in[2];
    const float* cw_b  = (const float*)d_in[3];
    const float* sw_W1 = (const float*)d_in[4];
    const float* sw_b1 = (const float*)d_in[5];
    const float* sw_W2 = (const float*)d_in[6];
    const float* sw_b2 = (const float*)d_in[7];
    const float* mw_W1 = (const float*)d_in[8];
    const float* mw_b1 = (const float*)d_in[9];
    const float* mw_W2 = (const float*)d_in[10];
    const float* mw_b2 = (const float*)d_in[11];

    float* out      = (float*)d_out;
    float* out_q    = out;
    float* out_wc   = out + (size_t)Bb * NQ * D;
    float* out_attn = out + 2 * (size_t)Bb * NQ * D;

    float *psm, *pcom, *ppb;
    __half *pmat, *pq16, *pqm, *pctx16, *pctxT, *pattn16, *pd16, *pcom16, *phs16, *pw16;
    cudaGetSymbolAddress((void**)&psm,     g_smooth);
    cudaGetSymbolAddress((void**)&pcom,    g_common);
    cudaGetSymbolAddress((void**)&ppb,     g_pb);
    cudaGetSymbolAddress((void**)&pmat,    g_mat16);
    cudaGetSymbolAddress((void**)&pq16,    g_q16);
    cudaGetSymbolAddress((void**)&pqm,     g_qm16);
    cudaGetSymbolAddress((void**)&pctx16,  g_ctx16);
    cudaGetSymbolAddress((void**)&pctxT,   g_ctxT16);
    cudaGetSymbolAddress((void**)&pattn16, g_attn16);
    cudaGetSymbolAddress((void**)&pd16,    g_d16);
    cudaGetSymbolAddress((void**)&pcom16,  g_com16);
    cudaGetSymbolAddress((void**)&phs16,   g_hs16);
    cudaGetSymbolAddress((void**)&pw16,    g_w16);

    cudaFuncSetAttribute(hgemm<1>, cudaFuncAttributeMaxDynamicSharedMemorySize, SMEM_BYTES);
    cudaFuncSetAttribute(hgemm<2>, cudaFuncAttributeMaxDynamicSharedMemorySize, SMEM_BYTES);
    cudaFuncSetAttribute(hgemm<3>, cudaFuncAttributeMaxDynamicSharedMemorySize, SMEM_BYTES);
    cudaFuncSetAttribute(hgemm<4>, cudaFuncAttributeMaxDynamicSharedMemorySize, SMEM_BYTES);
    cudaFuncSetAttribute(hgemm<5>, cudaFuncAttributeMaxDynamicSharedMemorySize, SMEM_BYTES);
    cudaFuncSetAttribute(attn_fused, cudaFuncAttributeMaxDynamicSharedMemorySize, AT_SMEM);

    // prep; attn_fused at launch #3 so ncu's capture slot profiles a GEMM
    init_kernel<<<(Bb * NQ * D / 4 + 255) / 256, 256>>>(query, pmat, psm, pq16, pqm);
    convert_kernel<<<(Bb * NC * D / 4 + 255) / 256, 256>>>(ctx, pctx16, Bb * NC * D);
    transpose_ctx<<<dim3(D / 32, NC / 32, Bb), dim3(32, 8)>>>(ctx, pctxT);
    attn_fused<<<Bb, 512, AT_SMEM>>>(pctx16, pqm, psm, pattn16, nullptr);   // scan, iter 0
    transpose_weights<<<1856, dim3(32, 8)>>>(cw_W, sw_W1, mw_W1, mw_W2, pw16);
    pack_bias<<<(2 * W1N + 255) / 256, 256>>>(mw_b1, sw_b1, ppb);

    for (int i = 0; i < 2; i++) {
        // d16 = (q - attn@ctx)^2
        hgemm<1><<<dim3(8, 2, Bb), 512, SMEM_BYTES>>>(
            pattn16, pctxT, nullptr, pd16, pq16, nullptr, nullptr,
            NC, NC, D, (size_t)NQ * NC, (size_t)NC * D, (size_t)NQ * D);
        // common = d16 @ cw_W + b (f32)
        hgemm<3><<<dim3(2, 256, 1), 512, SMEM_BYTES>>>(
            pd16, pw16 + W_CW + (size_t)i * AD * D, cw_b + (size_t)i * AD, pcom,
            nullptr, nullptr, nullptr, D, D, AD, 0, 0, 0);
        l2norm256_kernel<<<Bb * NQ / 8, 256>>>(pcom, pcom16);
        // fused W1: [h | sh] = tanh(com16 @ [mw1|sw1] + [b])
        hgemm<4><<<dim3(5, 256, 1), 512, SMEM_BYTES>>>(
            pcom16, pw16 + W_W1 + (size_t)i * W1N * AD, ppb + (size_t)i * W1N, phs16,
            nullptr, nullptr, nullptr, AD, AD, W1N, 0, 0, 0);
        sw_reduce_kernel<<<Bb * NQ / 8, 256>>>(phs16, sw_W2 + (size_t)i * HD, sw_b2 + i, psm);
        // matrix update
        hgemm<5><<<dim3(8, 256, 1), 512, SMEM_BYTES>>>(
            phs16, pw16 + W_W2 + (size_t)i * D * MD, mw_b2 + (size_t)i * D, nullptr,
            pq16, pmat, pqm, MD, W1N, D, 0, 0, 0);
        // next scan (iter i+1 or final)
        attn_fused<<<Bb, 512, AT_SMEM>>>(pctx16, pqm, psm, pattn16,
                                         (i == 1) ? out_attn : nullptr);
    }

    // final wc -> d_out
    hgemm<2><<<dim3(8, 2, Bb), 512, SMEM_BYTES>>>(
        pattn16, pctxT, nullptr, out_wc, nullptr, nullptr, nullptr,
        NC, NC, D, (size_t)NQ * NC, (size_t)NC * D, (size_t)NQ * D);

    cudaMemcpyAsync(out_q, query, (size_t)Bb * NQ * D * sizeof(float),
                    cudaMemcpyDeviceToDevice, 0);
}

// round 13
// speedup vs baseline: 1.0555x; 1.0111x over previous
#include <cuda_runtime.h>
#include <cuda_fp16.h>
#include <stdint.h>
#include <math.h>

// Problem constants
#define Bb 128
#define NQ 256
#define NC 128
#define D  1024
#define AD 256
#define HD 128
#define MD 512
#define W1N 640   // MD + HD fused N

// packed transposed weight offsets (halves)
#define W_CW  0
#define W_W1  (W_CW + 2 * AD * D)
#define W_W2  (W_W1 + 2 * W1N * AD)
#define W_TOT (W_W2 + 2 * D * MD)

// ---------------- scratch (device globals) ----------------
__device__ float  g_smooth[Bb * NQ];
__device__ float  g_common[Bb * NQ * AD];
__device__ float  g_pb[2 * W1N];
__device__ __half g_mat16[Bb * NQ * D];
__device__ __half g_q16[Bb * NQ * D];
__device__ __half g_qm16[Bb * NQ * D];
__device__ __half g_ctx16[Bb * NC * D];
__device__ __half g_ctxT16[Bb * D * NC];
__device__ __half g_attn16[Bb * NQ * NC];
__device__ __half g_d16[Bb * NQ * D];
__device__ __half g_com16[Bb * NQ * AD];
__device__ __half g_hs16[Bb * NQ * W1N];
__device__ __half g_w16[W_TOT];

// ---------------- utils ----------------
__device__ __forceinline__ float warp_sum(float v) {
#pragma unroll
    for (int o = 16; o > 0; o >>= 1) v += __shfl_xor_sync(0xffffffffu, v, o);
    return v;
}

__device__ __forceinline__ uint32_t smem_u32(const void* p) {
    uint32_t a;
    asm("{ .reg .u64 t; cvta.to.shared.u64 t, %1; cvt.u32.u64 %0, t; }" : "=r"(a) : "l"(p));
    return a;
}

__device__ __forceinline__ void cpa16(uint32_t dst, const void* src) {
    asm volatile("cp.async.cg.shared.global [%0], [%1], 16;" :: "r"(dst), "l"(src));
}
#define CPA_COMMIT() asm volatile("cp.async.commit_group;" ::: "memory")
#define CPA_WAIT1()  asm volatile("cp.async.wait_group 1;" ::: "memory")
#define CPA_WAIT0()  asm volatile("cp.async.wait_group 0;" ::: "memory")

__device__ __forceinline__ void ldm4(uint32_t* r, uint32_t a) {
    asm volatile("ldmatrix.sync.aligned.m8n8.x4.shared.b16 {%0,%1,%2,%3}, [%4];"
        : "=r"(r[0]), "=r"(r[1]), "=r"(r[2]), "=r"(r[3]) : "r"(a));
}

__device__ __forceinline__ void mma16(float* c, const uint32_t* a, const uint32_t* b) {
    asm volatile(
        "mma.sync.aligned.m16n8k16.row.col.f32.f16.f16.f32 "
        "{%0,%1,%2,%3},{%4,%5,%6,%7},{%8,%9},{%0,%1,%2,%3};"
        : "+f"(c[0]), "+f"(c[1]), "+f"(c[2]), "+f"(c[3])
        : "r"(a[0]), "r"(a[1]), "r"(a[2]), "r"(a[3]), "r"(b[0]), "r"(b[1]));
}

// epilogue helper
template<int EPI>
__device__ __forceinline__ void epi_store(
    float v0, float v1, size_t o, int n,
    const float* bias, void* Cout,
    const __half* q16, __half* mat16, __half* qm16)
{
    if (EPI == 1) {
        __half2 q2 = *(const __half2*)(q16 + o);
        float t0 = __half2float(__low2half(q2)) - v0;
        float t1 = __half2float(__high2half(q2)) - v1;
        *(__half2*)((__half*)Cout + o) = __floats2half2_rn(t0 * t0, t1 * t1);
    } else if (EPI == 2) {
        float2 w = {v0, v1};
        *(float2*)((float*)Cout + o) = w;
    } else if (EPI == 3) {
        float2 w = {v0 + __ldg(bias + n), v1 + __ldg(bias + n + 1)};
        *(float2*)((float*)Cout + o) = w;
    } else if (EPI == 4) {
        *(__half2*)((__half*)Cout + o) =
            __floats2half2_rn(tanhf(v0 + __ldg(bias + n)),
                              tanhf(v1 + __ldg(bias + n + 1)));
    } else {
        __half2 old2 = *(__half2*)(mat16 + o);
        __half2 q2 = *(const __half2*)(q16 + o);
        float n0v = fminf(1.0f, fmaxf(-1.0f,
            tanhf(v0 + __ldg(bias + n)) + __half2float(__low2half(old2))));
        float n1v = fminf(1.0f, fmaxf(-1.0f,
            tanhf(v1 + __ldg(bias + n + 1)) + __half2float(__high2half(old2))));
        *(__half2*)(mat16 + o) = __floats2half2_rn(n0v, n1v);
        *(__half2*)(qm16 + o) = __floats2half2_rn(
            __half2float(__low2half(q2)) * n0v,
            __half2float(__high2half(q2)) * n1v);
    }
}

// ====== GEMM: 128x128 tile, 256 thr, warp tile 32x64 (R10 shape), 2 CTA/SM,
// ====== with register-level fragment double-buffering in the inner loop.
#define STAGE_BYTES 32768
#define SMEM_BYTES  (3 * STAGE_BYTES)
template<int EPI>
__global__ void __launch_bounds__(256, 2) hgemm(
    const __half* __restrict__ A, const __half* __restrict__ Bw,
    const float* __restrict__ bias, void* __restrict__ Cout,
    const __half* __restrict__ q16, __half* __restrict__ mat16,
    __half* __restrict__ qm16,
    int K, int lda, int ldc, size_t sA, size_t sB, size_t sC)
{
    extern __shared__ __half smemh[];
    const uint32_t sbase = smem_u32(smemh);

    const int tid = threadIdx.x;
    const int lane = tid & 31, warp = tid >> 5;
    const int wm = (warp & 3) * 32, wn = (warp >> 2) * 64;
    const int z = blockIdx.z;
    const int m0 = blockIdx.y * 128, n0 = blockIdx.x * 128;

    const __half* Ab = A + (size_t)z * sA;
    const __half* Bp = Bw + (size_t)z * sB;

    const int ar = tid & 127, acb = (tid >> 7) * 4;
    const int NCH = K >> 6;

    float acc[2][8][4];
#pragma unroll
    for (int i = 0; i < 2; i++)
#pragma unroll
        for (int j = 0; j < 8; j++)
#pragma unroll
            for (int r = 0; r < 4; r++) acc[i][j][r] = 0.0f;

    auto load_chunk = [&](int stage, int ch) {
        const uint32_t Abase = sbase + stage * STAGE_BYTES;
        const uint32_t Bbase = Abase + 16384;
        const __half* ga = Ab + (size_t)(m0 + ar) * lda + ch * 64 + acb * 8;
        const __half* gb = Bp + (size_t)(n0 + ar) * K + ch * 64 + acb * 8;
#pragma unroll
        for (int j = 0; j < 4; j++) {
            int c = acb + j;
            uint32_t sw = ((uint32_t)(c ^ (ar & 7))) << 4;
            cpa16(Abase + ar * 128 + sw, ga + j * 8);
            cpa16(Bbase + ar * 128 + sw, gb + j * 8);
        }
    };

    auto compute = [&](int stage) {
        const uint32_t Abase = sbase + stage * STAGE_BYTES;
        const uint32_t Bbase = Abase + 16384;

        uint32_t aF[2][2][4];   // [buf][mi][frag]
        uint32_t bF[2][4][4];   // [buf][nb][frag]

        // prime s16 = 0 fragments
        {
            const int c = (lane >> 4);
#pragma unroll
            for (int mi = 0; mi < 2; mi++) {
                int row = wm + mi * 16 + (lane & 15);
                ldm4(aF[0][mi], Abase + row * 128 + (((uint32_t)(c ^ (row & 7))) << 4));
            }
#pragma unroll
            for (int nb = 0; nb < 4; nb++) {
                int row = wn + nb * 16 + (lane & 15);
                ldm4(bF[0][nb], Bbase + row * 128 + (((uint32_t)(c ^ (row & 7))) << 4));
            }
        }

#pragma unroll
        for (int s16 = 0; s16 < 4; s16++) {
            const int cur = s16 & 1, nxt = cur ^ 1;
            if (s16 < 3) {
                const int c = (s16 + 1) * 2 + (lane >> 4);
#pragma unroll
                for (int mi = 0; mi < 2; mi++) {
                    int row = wm + mi * 16 + (lane & 15);
                    ldm4(aF[nxt][mi], Abase + row * 128 + (((uint32_t)(c ^ (row & 7))) << 4));
                }
#pragma unroll
                for (int nb = 0; nb < 4; nb++) {
                    int row = wn + nb * 16 + (lane & 15);
                    ldm4(bF[nxt][nb], Bbase + row * 128 + (((uint32_t)(c ^ (row & 7))) << 4));
                }
            }
#pragma unroll
            for (int mi = 0; mi < 2; mi++)
#pragma unroll
                for (int nb = 0; nb < 4; nb++) {
                    uint32_t b0[2] = {bF[cur][nb][0], bF[cur][nb][2]};
                    uint32_t b1[2] = {bF[cur][nb][1], bF[cur][nb][3]};
                    mma16(acc[mi][2 * nb], aF[cur][mi], b0);
                    mma16(acc[mi][2 * nb + 1], aF[cur][mi], b1);
                }
        }
    };

    load_chunk(0, 0);
    CPA_COMMIT();
    if (NCH > 1) { load_chunk(1, 1); CPA_COMMIT(); }

    for (int i = 0; i < NCH; i++) {
        if (i + 2 < NCH) { CPA_WAIT1(); } else { CPA_WAIT0(); }
        __syncthreads();
        if (i + 2 < NCH) {
            load_chunk((i + 2) % 3, i + 2);
            CPA_COMMIT();
        }
        compute(i % 3);
    }

    const int g = lane >> 2, tg = lane & 3;
#pragma unroll
    for (int mi = 0; mi < 2; mi++) {
#pragma unroll
        for (int ni = 0; ni < 8; ni++) {
            int n = n0 + wn + ni * 8 + 2 * tg;
#pragma unroll
            for (int hh = 0; hh < 2; hh++) {
                int m = m0 + wm + mi * 16 + g + hh * 8;
                size_t o = (size_t)z * sC + (size_t)m * ldc + n;
                epi_store<EPI>(acc[mi][ni][hh * 2], acc[mi][ni][hh * 2 + 1],
                               o, n, bias, Cout, q16, mat16, qm16);
            }
        }
    }
}

// ---------------- fused attention scan (unchanged) ----------------
#define AT_STAGE   49152
#define AT_SMSTR   257
#define AT_SMEM    (3 * AT_STAGE)
__global__ void __launch_bounds__(512, 1) attn_fused(
    const __half* __restrict__ ctx16, const __half* __restrict__ qm16,
    const float* __restrict__ smooth,
    __half* __restrict__ a16, float* __restrict__ a32)
{
    extern __shared__ __half smemh[];
    const uint32_t sbase = smem_u32(smemh);
    float* smf = (float*)smemh;
    float* sinv = smf + NC * AT_SMSTR;

    const int tid = threadIdx.x;
    const int lane = tid & 31, warp = tid >> 5;
    const int wm = (warp & 3) * 32, wn = (warp >> 2) * 64;
    const int b = blockIdx.x;

    const __half* Ab = ctx16 + (size_t)b * NC * D;
    const __half* Bp = qm16 + (size_t)b * NQ * D;

    const int arow = tid >> 2, ac0 = (tid & 3) * 2;
    const int brow = tid >> 1, bc0 = (tid & 1) * 4;

    float acc[2][8][4];
#pragma unroll
    for (int i = 0; i < 2; i++)
#pragma unroll
        for (int j = 0; j < 8; j++)
#pragma unroll
            for (int r = 0; r < 4; r++) acc[i][j][r] = 0.0f;

    auto load_chunk = [&](int stage, int ch) {
        const uint32_t Abase = sbase + stage * AT_STAGE;
        const uint32_t Bbase = Abase + 16384;
        const __half* ga = Ab + (size_t)arow * D + ch * 64 + ac0 * 8;
#pragma unroll
        for (int j = 0; j < 2; j++) {
            int c = ac0 + j;
            cpa16(Abase + arow * 128 + (((uint32_t)(c ^ (arow & 7))) << 4), ga + j * 8);
        }
        const __half* gb = Bp + (size_t)brow * D + ch * 64 + bc0 * 8;
#pragma unroll
        for (int j = 0; j < 4; j++) {
            int c = bc0 + j;
            cpa16(Bbase + brow * 128 + (((uint32_t)(c ^ (brow & 7))) << 4), gb + j * 8);
        }
    };

    auto compute = [&](int stage) {
        const uint32_t Abase = sbase + stage * AT_STAGE;
        const uint32_t Bbase = Abase + 16384;
#pragma unroll
        for (int s16 = 0; s16 < 4; s16++) {
            uint32_t a[2][4];
#pragma unroll
            for (int mi = 0; mi < 2; mi++) {
                int row = wm + mi * 16 + (lane & 15);
                int c = s16 * 2 + (lane >> 4);
                ldm4(a[mi], Abase + row * 128 + (((uint32_t)(c ^ (row & 7))) << 4));
            }
            uint32_t bf[4][4];
#pragma unroll
            for (int nb = 0; nb < 4; nb++) {
                int row = wn + nb * 16 + (lane & 15);
                int c = s16 * 2 + (lane >> 4);
                ldm4(bf[nb], Bbase + row * 128 + (((uint32_t)(c ^ (row & 7))) << 4));
            }
#pragma unroll
            for (int mi = 0; mi < 2; mi++)
#pragma unroll
                for (int nb = 0; nb < 4; nb++) {
                    uint32_t b0[2] = {bf[nb][0], bf[nb][2]};
                    uint32_t b1[2] = {bf[nb][1], bf[nb][3]};
                    mma16(acc[mi][2 * nb], a[mi], b0);
                    mma16(acc[mi][2 * nb + 1], a[mi], b1);
                }
        }
    };

    const int NCH = D >> 6;
    load_chunk(0, 0);
    CPA_COMMIT();
    load_chunk(1, 1);
    CPA_COMMIT();
    for (int i = 0; i < NCH; i++) {
        if (i + 2 < NCH) { CPA_WAIT1(); } else { CPA_WAIT0(); }
        __syncthreads();
        if (i + 2 < NCH) {
            load_chunk((i + 2) % 3, i + 2);
            CPA_COMMIT();
        }
        compute(i % 3);
    }

    __syncthreads();
    const int g = lane >> 2, tg = lane & 3;
#pragma unroll
    for (int mi = 0; mi < 2; mi++) {
#pragma unroll
        for (int ni = 0; ni < 8; ni++) {
            int n = wn + ni * 8 + 2 * tg;
#pragma unroll
            for (int hh = 0; hh < 2; hh++) {
                int m = wm + mi * 16 + g + hh * 8;
                float v0 = acc[mi][ni][hh * 2 + 0];
                float v1 = acc[mi][ni][hh * 2 + 1];
                smf[m * AT_SMSTR + n]     = (v0 >= 0.0f) ? v0 : 0.1f * v0;
                smf[m * AT_SMSTR + n + 1] = (v1 >= 0.0f) ? v1 : 0.1f * v1;
            }
        }
    }
    __syncthreads();

#pragma unroll
    for (int r = 0; r < 8; r++) {
        int c = warp * 8 + r;
        const float* p = smf + c * AT_SMSTR;
        float s = 0.0f;
#pragma unroll
        for (int j = 0; j < 8; j++) {
            float x = p[lane + 32 * j];
            s += x * x;
        }
        s = warp_sum(s);
        if (lane == 0) sinv[c] = 1.0f / (sqrtf(s) + 1e-8f);
    }
    __syncthreads();

    for (int qi = warp; qi < NQ; qi += 16) {
        float sf = smooth[b * NQ + qi];
        float v0 = smf[(lane)      * AT_SMSTR + qi] * sinv[lane]      * sf;
        float v1 = smf[(lane + 32) * AT_SMSTR + qi] * sinv[lane + 32] * sf;
        float v2 = smf[(lane + 64) * AT_SMSTR + qi] * sinv[lane + 64] * sf;
        float v3 = smf[(lane + 96) * AT_SMSTR + qi] * sinv[lane + 96] * sf;
        float mx = fmaxf(fmaxf(v0, v1), fmaxf(v2, v3));
#pragma unroll
        for (int o = 16; o > 0; o >>= 1) mx = fmaxf(mx, __shfl_xor_sync(0xffffffffu, mx, o));
        float e0 = expf(v0 - mx), e1 = expf(v1 - mx), e2 = expf(v2 - mx), e3 = expf(v3 - mx);
        float s = warp_sum(e0 + e1 + e2 + e3);
        float inv = 1.0f / s;
        size_t base = ((size_t)b * NQ + qi) * NC;
        a16[base + lane]      = __float2half_rn(e0 * inv);
        a16[base + lane + 32] = __float2half_rn(e1 * inv);
        a16[base + lane + 64] = __float2half_rn(e2 * inv);
        a16[base + lane + 96] = __float2half_rn(e3 * inv);
        if (a32) {
            a32[base + lane]      = e0 * inv;
            a32[base + lane + 32] = e1 * inv;
            a32[base + lane + 64] = e2 * inv;
            a32[base + lane + 96] = e3 * inv;
        }
    }
}

// ---------------- transposes ----------------
__device__ __forceinline__ void tr_tile(const float* s, __half* d, int R, int C,
                                        int bx, int by) {
    __shared__ float t[32][33];
    int r0 = by * 32, c0 = bx * 32;
    for (int j = threadIdx.y; j < 32; j += 8)
        t[j][threadIdx.x] = s[(size_t)(r0 + j) * C + c0 + threadIdx.x];
    __syncthreads();
    for (int j = threadIdx.y; j < 32; j += 8)
        d[(size_t)(c0 + j) * R + r0 + threadIdx.x] = __float2half_rn(t[threadIdx.x][j]);
}

__global__ void transpose_ctx(const float* __restrict__ ctx, __half* __restrict__ dst) {
    const float* s = ctx + (size_t)blockIdx.z * NC * D;
    __half* d = dst + (size_t)blockIdx.z * NC * D;
    tr_tile(s, d, NC, D, blockIdx.x, blockIdx.y);
}

__global__ void transpose_weights(const float* __restrict__ cw, const float* __restrict__ sw1,
                                  const float* __restrict__ mw1, const float* __restrict__ mw2,
                                  __half* __restrict__ w16) {
    int blk = blockIdx.x;
    const float* src; __half* dst; int R, C;
    if (blk < 512) {
        int l = blk >> 8; blk &= 255;
        src = cw + (size_t)l * D * AD; dst = w16 + W_CW + (size_t)l * AD * D;
        R = D; C = AD;
    } else if (blk < 576) {
        blk -= 512; int l = blk >> 5; blk &= 31;
        src = sw1 + (size_t)l * AD * HD; dst = w16 + W_W1 + (size_t)l * W1N * AD + 512 * AD;
        R = AD; C = HD;
    } else if (blk < 832) {
        blk -= 576; int l = blk >> 7; blk &= 127;
        src = mw1 + (size_t)l * AD * MD; dst = w16 + W_W1 + (size_t)l * W1N * AD;
        R = AD; C = MD;
    } else {
        blk -= 832; int l = blk >> 9; blk &= 511;
        src = mw2 + (size_t)l * MD * D; dst = w16 + W_W2 + (size_t)l * D * MD;
        R = MD; C = D;
    }
    int bx = blk % (C / 32), by = blk / (C / 32);
    tr_tile(src, dst, R, C, bx, by);
}

__global__ void pack_bias(const float* __restrict__ mw_b1, const float* __restrict__ sw_b1,
                          float* __restrict__ pb) {
    int i = blockIdx.x * blockDim.x + threadIdx.x;
    if (i < 2 * W1N) {
        int l = i / W1N, n = i % W1N;
        pb[i] = (n < MD) ? mw_b1[l * MD + n] : sw_b1[l * HD + n - MD];
    }
}

// ---------------- elementwise kernels ----------------
__global__ void init_kernel(const float* __restrict__ query,
                            __half* __restrict__ mat16, float* __restrict__ smooth,
                            __half* __restrict__ q16, __half* __restrict__ qm16) {
    size_t i = ((size_t)blockIdx.x * blockDim.x + threadIdx.x) * 4;
    if (i < (size_t)Bb * NQ * D) {
        float4 q = *(const float4*)(query + i);
        __half2 h0 = __floats2half2_rn(q.x, q.y);
        __half2 h1 = __floats2half2_rn(q.z, q.w);
        __half2 one2 = __floats2half2_rn(1.0f, 1.0f);
        *(__half2*)(q16 + i)      = h0;
        *(__half2*)(q16 + i + 2)  = h1;
        *(__half2*)(qm16 + i)     = h0;
        *(__half2*)(qm16 + i + 2) = h1;
        *(__half2*)(mat16 + i)     = one2;
        *(__half2*)(mat16 + i + 2) = one2;
    }
    if (i < (size_t)Bb * NQ * 4) smooth[i / 4] = 10.0f;
}

__global__ void convert_kernel(const float* __restrict__ src, __half* __restrict__ dst, int n) {
    int i = (blockIdx.x * blockDim.x + threadIdx.x) * 4;
    if (i < n) {
        float4 v = *(const float4*)(src + i);
        *(__half2*)(dst + i)     = __floats2half2_rn(v.x, v.y);
        *(__half2*)(dst + i + 2) = __floats2half2_rn(v.z, v.w);
    }
}

__global__ void l2norm256_kernel(const float* __restrict__ X, __half* __restrict__ Y) {
    int row = blockIdx.x * 8 + (threadIdx.x >> 5);
    int lane = threadIdx.x & 31;
    const float* p = X + (size_t)row * AD;
    float vals[8];
    float s = 0.0f;
#pragma unroll
    for (int j = 0; j < 8; j++) {
        vals[j] = p[lane + 32 * j];
        s += vals[j] * vals[j];
    }
    s = warp_sum(s);
    float inv = 1.0f / (sqrtf(s) + 1e-8f);
    __half* y = Y + (size_t)row * AD;
#pragma unroll
    for (int j = 0; j < 8; j++)
        y[lane + 32 * j] = __float2half_rn(vals[j] * inv);
}

__global__ void sw_reduce_kernel(const __half* __restrict__ hs, const float* __restrict__ w2,
                                 const float* __restrict__ b2, float* __restrict__ smooth)
{
    int row = blockIdx.x * 8 + (threadIdx.x >> 5);
    int lane = threadIdx.x & 31;
    const __half* r = hs + (size_t)row * W1N + MD;
    float s = __half2float(r[lane]) * w2[lane]
            + __half2float(r[lane + 32]) * w2[lane + 32]
            + __half2float(r[lane + 64]) * w2[lane + 64]
            + __half2float(r[lane + 96]) * w2[lane + 96];
    s = warp_sum(s);
    if (lane == 0) smooth[row] = fmaxf(0.0f, s + b2[0] + smooth[row]);
}

// ---------------- orchestration ----------------
extern "C" void kernel_launch(void* const* d_in, const int* in_sizes, int n_in,
                              void* d_out, int out_size)
{
    const float* query = (const float*)d_in[0];
    const float* ctx   = (const float*)d_in[1];
    const float* cw_W  = (const float*)d_in[2];
    const float* cw_b  = (const float*)d_in[3];
    const float* sw_W1 = (const float*)d_in[4];
    const float* sw_b1 = (const float*)d_in[5];
    const float* sw_W2 = (const float*)d_in[6];
    const float* sw_b2 = (const float*)d_in[7];
    const float* mw_W1 = (const float*)d_in[8];
    const float* mw_b1 = (const float*)d_in[9];
    const float* mw_W2 = (const float*)d_in[10];
    const float* mw_b2 = (const float*)d_in[11];

    float* out      = (float*)d_out;
    float* out_q    = out;
    float* out_wc   = out + (size_t)Bb * NQ * D;
    float* out_attn = out + 2 * (size_t)Bb * NQ * D;

    float *psm, *pcom, *ppb;
    __half *pmat, *pq16, *pqm, *pctx16, *pctxT, *pattn16, *pd16, *pcom16, *phs16, *pw16;
    cudaGetSymbolAddress((void**)&psm,     g_smooth);
    cudaGetSymbolAddress((void**)&pcom,    g_common);
    cudaGetSymbolAddress((void**)&ppb,     g_pb);
    cudaGetSymbolAddress((void**)&pmat,    g_mat16);
    cudaGetSymbolAddress((void**)&pq16,    g_q16);
    cudaGetSymbolAddress((void**)&pqm,     g_qm16);
    cudaGetSymbolAddress((void**)&pctx16,  g_ctx16);
    cudaGetSymbolAddress((void**)&pctxT,   g_ctxT16);
    cudaGetSymbolAddress((void**)&pattn16, g_attn16);
    cudaGetSymbolAddress((void**)&pd16,    g_d16);
    cudaGetSymbolAddress((void**)&pcom16,  g_com16);
    cudaGetSymbolAddress((void**)&phs16,   g_hs16);
    cudaGetSymbolAddress((void**)&pw16,    g_w16);

    cudaFuncSetAttribute(hgemm<1>, cudaFuncAttributeMaxDynamicSharedMemorySize, SMEM_BYTES);
    cudaFuncSetAttribute(hgemm<2>, cudaFuncAttributeMaxDynamicSharedMemorySize, SMEM_BYTES);
    cudaFuncSetAttribute(hgemm<3>, cudaFuncAttributeMaxDynamicSharedMemorySize, SMEM_BYTES);
    cudaFuncSetAttribute(hgemm<4>, cudaFuncAttributeMaxDynamicSharedMemorySize, SMEM_BYTES);
    cudaFuncSetAttribute(hgemm<5>, cudaFuncAttributeMaxDynamicSharedMemorySize, SMEM_BYTES);
    cudaFuncSetAttribute(attn_fused, cudaFuncAttributeMaxDynamicSharedMemorySize, AT_SMEM);

    // prep; attn_fused at launch #3 keeps the GEMM in ncu's capture slot
    init_kernel<<<(Bb * NQ * D / 4 + 255) / 256, 256>>>(query, pmat, psm, pq16, pqm);
    convert_kernel<<<(Bb * NC * D / 4 + 255) / 256, 256>>>(ctx, pctx16, Bb * NC * D);
    transpose_ctx<<<dim3(D / 32, NC / 32, Bb), dim3(32, 8)>>>(ctx, pctxT);
    attn_fused<<<Bb, 512, AT_SMEM>>>(pctx16, pqm, psm, pattn16, nullptr);   // scan, iter 0
    transpose_weights<<<1856, dim3(32, 8)>>>(cw_W, sw_W1, mw_W1, mw_W2, pw16);
    pack_bias<<<(2 * W1N + 255) / 256, 256>>>(mw_b1, sw_b1, ppb);

    for (int i = 0; i < 2; i++) {
        // d16 = (q - attn@ctx)^2
        hgemm<1><<<dim3(8, 2, Bb), 256, SMEM_BYTES>>>(
            pattn16, pctxT, nullptr, pd16, pq16, nullptr, nullptr,
            NC, NC, D, (size_t)NQ * NC, (size_t)NC * D, (size_t)NQ * D);
        // common = d16 @ cw_W + b (f32)
        hgemm<3><<<dim3(2, 256, 1), 256, SMEM_BYTES>>>(
            pd16, pw16 + W_CW + (size_t)i * AD * D, cw_b + (size_t)i * AD, pcom,
            nullptr, nullptr, nullptr, D, D, AD, 0, 0, 0);
        l2norm256_kernel<<<Bb * NQ / 8, 256>>>(pcom, pcom16);
        // fused W1: [h | sh] = tanh(com16 @ [mw1|sw1] + [b])
        hgemm<4><<<dim3(5, 256, 1), 256, SMEM_BYTES>>>(
            pcom16, pw16 + W_W1 + (size_t)i * W1N * AD, ppb + (size_t)i * W1N, phs16,
            nullptr, nullptr, nullptr, AD, AD, W1N, 0, 0, 0);
        sw_reduce_kernel<<<Bb * NQ / 8, 256>>>(phs16, sw_W2 + (size_t)i * HD, sw_b2 + i, psm);
        // matrix update
        hgemm<5><<<dim3(8, 256, 1), 256, SMEM_BYTES>>>(
            phs16, pw16 + W_W2 + (size_t)i * D * MD, mw_b2 + (size_t)i * D, nullptr,
            pq16, pmat, pqm, MD, W1N, D, 0, 0, 0);
        // next scan (iter i+1 or final)
        attn_fused<<<Bb, 512, AT_SMEM>>>(pctx16, pqm, psm, pattn16,
                                         (i == 1) ? out_attn : nullptr);
    }

    // final wc -> d_out
    hgemm<2><<<dim3(8, 2, Bb), 256, SMEM_BYTES>>>(
        pattn16, pctxT, nullptr, out_wc, nullptr, nullptr, nullptr,
        NC, NC, D, (size_t)NQ * NC, (size_t)NC * D, (size_t)NQ * D);

    cudaMemcpyAsync(out_q, query, (size_t)Bb * NQ * D * sizeof(float),
                    cudaMemcpyDeviceToDevice, 0);
}

// round 14
// speedup vs baseline: 1.0681x; 1.0119x over previous
#include <cuda_runtime.h>
#include <cuda_fp16.h>
#include <stdint.h>
#include <math.h>

// Problem constants
#define Bb 128
#define NQ 256
#define NC 128
#define D  1024
#define AD 256
#define HD 128
#define MD 512
#define W1N 640   // MD + HD fused N

// packed transposed weight offsets (halves)
#define W_CW  0
#define W_W1  (W_CW + 2 * AD * D)
#define W_W2  (W_W1 + 2 * W1N * AD)
#define W_TOT (W_W2 + 2 * D * MD)

// ---------------- scratch (device globals) ----------------
__device__ float  g_smooth[Bb * NQ];
__device__ float  g_common[Bb * NQ * AD];
__device__ float  g_pb[2 * W1N];
__device__ __half g_mat16[Bb * NQ * D];
__device__ __half g_q16[Bb * NQ * D];
__device__ __half g_qm16[Bb * NQ * D];
__device__ __half g_ctx16[Bb * NC * D];
__device__ __half g_ctxT16[Bb * D * NC];
__device__ __half g_attn16[Bb * NQ * NC];
__device__ __half g_d16[Bb * NQ * D];
__device__ __half g_com16[Bb * NQ * AD];
__device__ __half g_hs16[Bb * NQ * W1N];
__device__ __half g_w16[W_TOT];

// ---------------- utils ----------------
__device__ __forceinline__ float warp_sum(float v) {
#pragma unroll
    for (int o = 16; o > 0; o >>= 1) v += __shfl_xor_sync(0xffffffffu, v, o);
    return v;
}

__device__ __forceinline__ uint32_t smem_u32(const void* p) {
    uint32_t a;
    asm("{ .reg .u64 t; cvta.to.shared.u64 t, %1; cvt.u32.u64 %0, t; }" : "=r"(a) : "l"(p));
    return a;
}

__device__ __forceinline__ void cpa16(uint32_t dst, const void* src) {
    asm volatile("cp.async.cg.shared.global [%0], [%1], 16;" :: "r"(dst), "l"(src));
}
#define CPA_COMMIT() asm volatile("cp.async.commit_group;" ::: "memory")
#define CPA_WAIT1()  asm volatile("cp.async.wait_group 1;" ::: "memory")
#define CPA_WAIT0()  asm volatile("cp.async.wait_group 0;" ::: "memory")

__device__ __forceinline__ void ldm4(uint32_t* r, uint32_t a) {
    asm volatile("ldmatrix.sync.aligned.m8n8.x4.shared.b16 {%0,%1,%2,%3}, [%4];"
        : "=r"(r[0]), "=r"(r[1]), "=r"(r[2]), "=r"(r[3]) : "r"(a));
}

__device__ __forceinline__ void mma16(float* c, const uint32_t* a, const uint32_t* b) {
    asm volatile(
        "mma.sync.aligned.m16n8k16.row.col.f32.f16.f16.f32 "
        "{%0,%1,%2,%3},{%4,%5,%6,%7},{%8,%9},{%0,%1,%2,%3};"
        : "+f"(c[0]), "+f"(c[1]), "+f"(c[2]), "+f"(c[3])
        : "r"(a[0]), "r"(a[1]), "r"(a[2]), "r"(a[3]), "r"(b[0]), "r"(b[1]));
}

// epilogue helper
template<int EPI>
__device__ __forceinline__ void epi_store(
    float v0, float v1, size_t o, int n,
    const float* bias, void* Cout,
    const __half* q16, __half* mat16, __half* qm16)
{
    if (EPI == 1) {
        __half2 q2 = *(const __half2*)(q16 + o);
        float t0 = __half2float(__low2half(q2)) - v0;
        float t1 = __half2float(__high2half(q2)) - v1;
        *(__half2*)((__half*)Cout + o) = __floats2half2_rn(t0 * t0, t1 * t1);
    } else if (EPI == 2) {
        float2 w = {v0, v1};
        *(float2*)((float*)Cout + o) = w;
    } else if (EPI == 3) {
        float2 w = {v0 + __ldg(bias + n), v1 + __ldg(bias + n + 1)};
        *(float2*)((float*)Cout + o) = w;
    } else if (EPI == 4) {
        *(__half2*)((__half*)Cout + o) =
            __floats2half2_rn(tanhf(v0 + __ldg(bias + n)),
                              tanhf(v1 + __ldg(bias + n + 1)));
    } else {
        __half2 old2 = *(__half2*)(mat16 + o);
        __half2 q2 = *(const __half2*)(q16 + o);
        float n0v = fminf(1.0f, fmaxf(-1.0f,
            tanhf(v0 + __ldg(bias + n)) + __half2float(__low2half(old2))));
        float n1v = fminf(1.0f, fmaxf(-1.0f,
            tanhf(v1 + __ldg(bias + n + 1)) + __half2float(__high2half(old2))));
        *(__half2*)(mat16 + o) = __floats2half2_rn(n0v, n1v);
        *(__half2*)(qm16 + o) = __floats2half2_rn(
            __half2float(__low2half(q2)) * n0v,
            __half2float(__high2half(q2)) * n1v);
    }
}

// ====== GEMM: 128x128 tile, 256 thr, warp tile 32x64, 2 CTA/SM (R13) ======
#define STAGE_BYTES 32768
#define SMEM_BYTES  (3 * STAGE_BYTES)
template<int EPI>
__global__ void __launch_bounds__(256, 2) hgemm(
    const __half* __restrict__ A, const __half* __restrict__ Bw,
    const float* __restrict__ bias, void* __restrict__ Cout,
    const __half* __restrict__ q16, __half* __restrict__ mat16,
    __half* __restrict__ qm16,
    int K, int lda, int ldc, size_t sA, size_t sB, size_t sC)
{
    extern __shared__ __half smemh[];
    const uint32_t sbase = smem_u32(smemh);

    const int tid = threadIdx.x;
    const int lane = tid & 31, warp = tid >> 5;
    const int wm = (warp & 3) * 32, wn = (warp >> 2) * 64;
    const int z = blockIdx.z;
    const int m0 = blockIdx.y * 128, n0 = blockIdx.x * 128;

    const __half* Ab = A + (size_t)z * sA;
    const __half* Bp = Bw + (size_t)z * sB;

    const int ar = tid & 127, acb = (tid >> 7) * 4;
    const int NCH = K >> 6;

    float acc[2][8][4];
#pragma unroll
    for (int i = 0; i < 2; i++)
#pragma unroll
        for (int j = 0; j < 8; j++)
#pragma unroll
            for (int r = 0; r < 4; r++) acc[i][j][r] = 0.0f;

    auto load_chunk = [&](int stage, int ch) {
        const uint32_t Abase = sbase + stage * STAGE_BYTES;
        const uint32_t Bbase = Abase + 16384;
        const __half* ga = Ab + (size_t)(m0 + ar) * lda + ch * 64 + acb * 8;
        const __half* gb = Bp + (size_t)(n0 + ar) * K + ch * 64 + acb * 8;
#pragma unroll
        for (int j = 0; j < 4; j++) {
            int c = acb + j;
            uint32_t sw = ((uint32_t)(c ^ (ar & 7))) << 4;
            cpa16(Abase + ar * 128 + sw, ga + j * 8);
            cpa16(Bbase + ar * 128 + sw, gb + j * 8);
        }
    };

    auto compute = [&](int stage) {
        const uint32_t Abase = sbase + stage * STAGE_BYTES;
        const uint32_t Bbase = Abase + 16384;

        uint32_t aF[2][2][4];
        uint32_t bF[2][4][4];
        {
            const int c = (lane >> 4);
#pragma unroll
            for (int mi = 0; mi < 2; mi++) {
                int row = wm + mi * 16 + (lane & 15);
                ldm4(aF[0][mi], Abase + row * 128 + (((uint32_t)(c ^ (row & 7))) << 4));
            }
#pragma unroll
            for (int nb = 0; nb < 4; nb++) {
                int row = wn + nb * 16 + (lane & 15);
                ldm4(bF[0][nb], Bbase + row * 128 + (((uint32_t)(c ^ (row & 7))) << 4));
            }
        }

#pragma unroll
        for (int s16 = 0; s16 < 4; s16++) {
            const int cur = s16 & 1, nxt = cur ^ 1;
            if (s16 < 3) {
                const int c = (s16 + 1) * 2 + (lane >> 4);
#pragma unroll
                for (int mi = 0; mi < 2; mi++) {
                    int row = wm + mi * 16 + (lane & 15);
                    ldm4(aF[nxt][mi], Abase + row * 128 + (((uint32_t)(c ^ (row & 7))) << 4));
                }
#pragma unroll
                for (int nb = 0; nb < 4; nb++) {
                    int row = wn + nb * 16 + (lane & 15);
                    ldm4(bF[nxt][nb], Bbase + row * 128 + (((uint32_t)(c ^ (row & 7))) << 4));
                }
            }
#pragma unroll
            for (int mi = 0; mi < 2; mi++)
#pragma unroll
                for (int nb = 0; nb < 4; nb++) {
                    uint32_t b0[2] = {bF[cur][nb][0], bF[cur][nb][2]};
                    uint32_t b1[2] = {bF[cur][nb][1], bF[cur][nb][3]};
                    mma16(acc[mi][2 * nb], aF[cur][mi], b0);
                    mma16(acc[mi][2 * nb + 1], aF[cur][mi], b1);
                }
        }
    };

    load_chunk(0, 0);
    CPA_COMMIT();
    if (NCH > 1) { load_chunk(1, 1); CPA_COMMIT(); }

    for (int i = 0; i < NCH; i++) {
        if (i + 2 < NCH) { CPA_WAIT1(); } else { CPA_WAIT0(); }
        __syncthreads();
        if (i + 2 < NCH) {
            load_chunk((i + 2) % 3, i + 2);
            CPA_COMMIT();
        }
        compute(i % 3);
    }

    const int g = lane >> 2, tg = lane & 3;
#pragma unroll
    for (int mi = 0; mi < 2; mi++) {
#pragma unroll
        for (int ni = 0; ni < 8; ni++) {
            int n = n0 + wn + ni * 8 + 2 * tg;
#pragma unroll
            for (int hh = 0; hh < 2; hh++) {
                int m = m0 + wm + mi * 16 + g + hh * 8;
                size_t o = (size_t)z * sC + (size_t)m * ldc + n;
                epi_store<EPI>(acc[mi][ni][hh * 2], acc[mi][ni][hh * 2 + 1],
                               o, n, bias, Cout, q16, mat16, qm16);
            }
        }
    }
}

// ---------------- fused attention scan (unchanged) ----------------
#define AT_STAGE   49152
#define AT_SMSTR   257
#define AT_SMEM    (3 * AT_STAGE)
__global__ void __launch_bounds__(512, 1) attn_fused(
    const __half* __restrict__ ctx16, const __half* __restrict__ qm16,
    const float* __restrict__ smooth,
    __half* __restrict__ a16, float* __restrict__ a32)
{
    extern __shared__ __half smemh[];
    const uint32_t sbase = smem_u32(smemh);
    float* smf = (float*)smemh;
    float* sinv = smf + NC * AT_SMSTR;

    const int tid = threadIdx.x;
    const int lane = tid & 31, warp = tid >> 5;
    const int wm = (warp & 3) * 32, wn = (warp >> 2) * 64;
    const int b = blockIdx.x;

    const __half* Ab = ctx16 + (size_t)b * NC * D;
    const __half* Bp = qm16 + (size_t)b * NQ * D;

    const int arow = tid >> 2, ac0 = (tid & 3) * 2;
    const int brow = tid >> 1, bc0 = (tid & 1) * 4;

    float acc[2][8][4];
#pragma unroll
    for (int i = 0; i < 2; i++)
#pragma unroll
        for (int j = 0; j < 8; j++)
#pragma unroll
            for (int r = 0; r < 4; r++) acc[i][j][r] = 0.0f;

    auto load_chunk = [&](int stage, int ch) {
        const uint32_t Abase = sbase + stage * AT_STAGE;
        const uint32_t Bbase = Abase + 16384;
        const __half* ga = Ab + (size_t)arow * D + ch * 64 + ac0 * 8;
#pragma unroll
        for (int j = 0; j < 2; j++) {
            int c = ac0 + j;
            cpa16(Abase + arow * 128 + (((uint32_t)(c ^ (arow & 7))) << 4), ga + j * 8);
        }
        const __half* gb = Bp + (size_t)brow * D + ch * 64 + bc0 * 8;
#pragma unroll
        for (int j = 0; j < 4; j++) {
            int c = bc0 + j;
            cpa16(Bbase + brow * 128 + (((uint32_t)(c ^ (brow & 7))) << 4), gb + j * 8);
        }
    };

    auto compute = [&](int stage) {
        const uint32_t Abase = sbase + stage * AT_STAGE;
        const uint32_t Bbase = Abase + 16384;
#pragma unroll
        for (int s16 = 0; s16 < 4; s16++) {
            uint32_t a[2][4];
#pragma unroll
            for (int mi = 0; mi < 2; mi++) {
                int row = wm + mi * 16 + (lane & 15);
                int c = s16 * 2 + (lane >> 4);
                ldm4(a[mi], Abase + row * 128 + (((uint32_t)(c ^ (row & 7))) << 4));
            }
            uint32_t bf[4][4];
#pragma unroll
            for (int nb = 0; nb < 4; nb++) {
                int row = wn + nb * 16 + (lane & 15);
                int c = s16 * 2 + (lane >> 4);
                ldm4(bf[nb], Bbase + row * 128 + (((uint32_t)(c ^ (row & 7))) << 4));
            }
#pragma unroll
            for (int mi = 0; mi < 2; mi++)
#pragma unroll
                for (int nb = 0; nb < 4; nb++) {
                    uint32_t b0[2] = {bf[nb][0], bf[nb][2]};
                    uint32_t b1[2] = {bf[nb][1], bf[nb][3]};
                    mma16(acc[mi][2 * nb], a[mi], b0);
                    mma16(acc[mi][2 * nb + 1], a[mi], b1);
                }
        }
    };

    const int NCH = D >> 6;
    load_chunk(0, 0);
    CPA_COMMIT();
    load_chunk(1, 1);
    CPA_COMMIT();
    for (int i = 0; i < NCH; i++) {
        if (i + 2 < NCH) { CPA_WAIT1(); } else { CPA_WAIT0(); }
        __syncthreads();
        if (i + 2 < NCH) {
            load_chunk((i + 2) % 3, i + 2);
            CPA_COMMIT();
        }
        compute(i % 3);
    }

    __syncthreads();
    const int g = lane >> 2, tg = lane & 3;
#pragma unroll
    for (int mi = 0; mi < 2; mi++) {
#pragma unroll
        for (int ni = 0; ni < 8; ni++) {
            int n = wn + ni * 8 + 2 * tg;
#pragma unroll
            for (int hh = 0; hh < 2; hh++) {
                int m = wm + mi * 16 + g + hh * 8;
                float v0 = acc[mi][ni][hh * 2 + 0];
                float v1 = acc[mi][ni][hh * 2 + 1];
                smf[m * AT_SMSTR + n]     = (v0 >= 0.0f) ? v0 : 0.1f * v0;
                smf[m * AT_SMSTR + n + 1] = (v1 >= 0.0f) ? v1 : 0.1f * v1;
            }
        }
    }
    __syncthreads();

#pragma unroll
    for (int r = 0; r < 8; r++) {
        int c = warp * 8 + r;
        const float* p = smf + c * AT_SMSTR;
        float s = 0.0f;
#pragma unroll
        for (int j = 0; j < 8; j++) {
            float x = p[lane + 32 * j];
            s += x * x;
        }
        s = warp_sum(s);
        if (lane == 0) sinv[c] = 1.0f / (sqrtf(s) + 1e-8f);
    }
    __syncthreads();

    for (int qi = warp; qi < NQ; qi += 16) {
        float sf = smooth[b * NQ + qi];
        float v0 = smf[(lane)      * AT_SMSTR + qi] * sinv[lane]      * sf;
        float v1 = smf[(lane + 32) * AT_SMSTR + qi] * sinv[lane + 32] * sf;
        float v2 = smf[(lane + 64) * AT_SMSTR + qi] * sinv[lane + 64] * sf;
        float v3 = smf[(lane + 96) * AT_SMSTR + qi] * sinv[lane + 96] * sf;
        float mx = fmaxf(fmaxf(v0, v1), fmaxf(v2, v3));
#pragma unroll
        for (int o = 16; o > 0; o >>= 1) mx = fmaxf(mx, __shfl_xor_sync(0xffffffffu, mx, o));
        float e0 = expf(v0 - mx), e1 = expf(v1 - mx), e2 = expf(v2 - mx), e3 = expf(v3 - mx);
        float s = warp_sum(e0 + e1 + e2 + e3);
        float inv = 1.0f / s;
        size_t base = ((size_t)b * NQ + qi) * NC;
        a16[base + lane]      = __float2half_rn(e0 * inv);
        a16[base + lane + 32] = __float2half_rn(e1 * inv);
        a16[base + lane + 64] = __float2half_rn(e2 * inv);
        a16[base + lane + 96] = __float2half_rn(e3 * inv);
        if (a32) {
            a32[base + lane]      = e0 * inv;
            a32[base + lane + 32] = e1 * inv;
            a32[base + lane + 64] = e2 * inv;
            a32[base + lane + 96] = e3 * inv;
        }
    }
}

// ---------------- transposes ----------------
__device__ __forceinline__ void tr_tile(const float* s, __half* d, int R, int C,
                                        int bx, int by) {
    __shared__ float t[32][33];
    int r0 = by * 32, c0 = bx * 32;
    for (int j = threadIdx.y; j < 32; j += 8)
        t[j][threadIdx.x] = s[(size_t)(r0 + j) * C + c0 + threadIdx.x];
    __syncthreads();
    for (int j = threadIdx.y; j < 32; j += 8)
        d[(size_t)(c0 + j) * R + r0 + threadIdx.x] = __float2half_rn(t[threadIdx.x][j]);
}

__global__ void transpose_ctx(const float* __restrict__ ctx, __half* __restrict__ dst) {
    const float* s = ctx + (size_t)blockIdx.z * NC * D;
    __half* d = dst + (size_t)blockIdx.z * NC * D;
    tr_tile(s, d, NC, D, blockIdx.x, blockIdx.y);
}

__global__ void transpose_weights(const float* __restrict__ cw, const float* __restrict__ sw1,
                                  const float* __restrict__ mw1, const float* __restrict__ mw2,
                                  __half* __restrict__ w16) {
    int blk = blockIdx.x;
    const float* src; __half* dst; int R, C;
    if (blk < 512) {
        int l = blk >> 8; blk &= 255;
        src = cw + (size_t)l * D * AD; dst = w16 + W_CW + (size_t)l * AD * D;
        R = D; C = AD;
    } else if (blk < 576) {
        blk -= 512; int l = blk >> 5; blk &= 31;
        src = sw1 + (size_t)l * AD * HD; dst = w16 + W_W1 + (size_t)l * W1N * AD + 512 * AD;
        R = AD; C = HD;
    } else if (blk < 832) {
        blk -= 576; int l = blk >> 7; blk &= 127;
        src = mw1 + (size_t)l * AD * MD; dst = w16 + W_W1 + (size_t)l * W1N * AD;
        R = AD; C = MD;
    } else {
        blk -= 832; int l = blk >> 9; blk &= 511;
        src = mw2 + (size_t)l * MD * D; dst = w16 + W_W2 + (size_t)l * D * MD;
        R = MD; C = D;
    }
    int bx = blk % (C / 32), by = blk / (C / 32);
    tr_tile(src, dst, R, C, bx, by);
}

__global__ void pack_bias(const float* __restrict__ mw_b1, const float* __restrict__ sw_b1,
                          float* __restrict__ pb) {
    int i = blockIdx.x * blockDim.x + threadIdx.x;
    if (i < 2 * W1N) {
        int l = i / W1N, n = i % W1N;
        pb[i] = (n < MD) ? mw_b1[l * MD + n] : sw_b1[l * HD + n - MD];
    }
}

// ---------------- elementwise kernels ----------------
__global__ void init_kernel(const float* __restrict__ query,
                            __half* __restrict__ mat16, float* __restrict__ smooth,
                            __half* __restrict__ q16, __half* __restrict__ qm16) {
    size_t i = ((size_t)blockIdx.x * blockDim.x + threadIdx.x) * 4;
    if (i < (size_t)Bb * NQ * D) {
        float4 q = *(const float4*)(query + i);
        __half2 h0 = __floats2half2_rn(q.x, q.y);
        __half2 h1 = __floats2half2_rn(q.z, q.w);
        __half2 one2 = __floats2half2_rn(1.0f, 1.0f);
        *(__half2*)(q16 + i)      = h0;
        *(__half2*)(q16 + i + 2)  = h1;
        *(__half2*)(qm16 + i)     = h0;
        *(__half2*)(qm16 + i + 2) = h1;
        *(__half2*)(mat16 + i)     = one2;
        *(__half2*)(mat16 + i + 2) = one2;
    }
    if (i < (size_t)Bb * NQ * 4) smooth[i / 4] = 10.0f;
}

__global__ void convert_kernel(const float* __restrict__ src, __half* __restrict__ dst, int n) {
    int i = (blockIdx.x * blockDim.x + threadIdx.x) * 4;
    if (i < n) {
        float4 v = *(const float4*)(src + i);
        *(__half2*)(dst + i)     = __floats2half2_rn(v.x, v.y);
        *(__half2*)(dst + i + 2) = __floats2half2_rn(v.z, v.w);
    }
}

__global__ void l2norm256_kernel(const float* __restrict__ X, __half* __restrict__ Y) {
    int row = blockIdx.x * 8 + (threadIdx.x >> 5);
    int lane = threadIdx.x & 31;
    const float* p = X + (size_t)row * AD;
    float vals[8];
    float s = 0.0f;
#pragma unroll
    for (int j = 0; j < 8; j++) {
        vals[j] = p[lane + 32 * j];
        s += vals[j] * vals[j];
    }
    s = warp_sum(s);
    float inv = 1.0f / (sqrtf(s) + 1e-8f);
    __half* y = Y + (size_t)row * AD;
#pragma unroll
    for (int j = 0; j < 8; j++)
        y[lane + 32 * j] = __float2half_rn(vals[j] * inv);
}

__global__ void sw_reduce_kernel(const __half* __restrict__ hs, const float* __restrict__ w2,
                                 const float* __restrict__ b2, float* __restrict__ smooth)
{
    int row = blockIdx.x * 8 + (threadIdx.x >> 5);
    int lane = threadIdx.x & 31;
    const __half* r = hs + (size_t)row * W1N + MD;
    float s = __half2float(r[lane]) * w2[lane]
            + __half2float(r[lane + 32]) * w2[lane + 32]
            + __half2float(r[lane + 64]) * w2[lane + 64]
            + __half2float(r[lane + 96]) * w2[lane + 96];
    s = warp_sum(s);
    if (lane == 0) smooth[row] = fmaxf(0.0f, s + b2[0] + smooth[row]);
}

// ---------------- orchestration (multi-stream overlap) ----------------
extern "C" void kernel_launch(void* const* d_in, const int* in_sizes, int n_in,
                              void* d_out, int out_size)
{
    const float* query = (const float*)d_in[0];
    const float* ctx   = (const float*)d_in[1];
    const float* cw_W  = (const float*)d_in[2];
    const float* cw_b  = (const float*)d_in[3];
    const float* sw_W1 = (const float*)d_in[4];
    const float* sw_b1 = (const float*)d_in[5];
    const float* sw_W2 = (const float*)d_in[6];
    const float* sw_b2 = (const float*)d_in[7];
    const float* mw_W1 = (const float*)d_in[8];
    const float* mw_b1 = (const float*)d_in[9];
    const float* mw_W2 = (const float*)d_in[10];
    const float* mw_b2 = (const float*)d_in[11];

    float* out      = (float*)d_out;
    float* out_q    = out;
    float* out_wc   = out + (size_t)Bb * NQ * D;
    float* out_attn = out + 2 * (size_t)Bb * NQ * D;

    float *psm, *pcom, *ppb;
    __half *pmat, *pq16, *pqm, *pctx16, *pctxT, *pattn16, *pd16, *pcom16, *phs16, *pw16;
    cudaGetSymbolAddress((void**)&psm,     g_smooth);
    cudaGetSymbolAddress((void**)&pcom,    g_common);
    cudaGetSymbolAddress((void**)&ppb,     g_pb);
    cudaGetSymbolAddress((void**)&pmat,    g_mat16);
    cudaGetSymbolAddress((void**)&pq16,    g_q16);
    cudaGetSymbolAddress((void**)&pqm,     g_qm16);
    cudaGetSymbolAddress((void**)&pctx16,  g_ctx16);
    cudaGetSymbolAddress((void**)&pctxT,   g_ctxT16);
    cudaGetSymbolAddress((void**)&pattn16, g_attn16);
    cudaGetSymbolAddress((void**)&pd16,    g_d16);
    cudaGetSymbolAddress((void**)&pcom16,  g_com16);
    cudaGetSymbolAddress((void**)&phs16,   g_hs16);
    cudaGetSymbolAddress((void**)&pw16,    g_w16);

    cudaFuncSetAttribute(hgemm<1>, cudaFuncAttributeMaxDynamicSharedMemorySize, SMEM_BYTES);
    cudaFuncSetAttribute(hgemm<2>, cudaFuncAttributeMaxDynamicSharedMemorySize, SMEM_BYTES);
    cudaFuncSetAttribute(hgemm<3>, cudaFuncAttributeMaxDynamicSharedMemorySize, SMEM_BYTES);
    cudaFuncSetAttribute(hgemm<4>, cudaFuncAttributeMaxDynamicSharedMemorySize, SMEM_BYTES);
    cudaFuncSetAttribute(hgemm<5>, cudaFuncAttributeMaxDynamicSharedMemorySize, SMEM_BYTES);
    cudaFuncSetAttribute(attn_fused, cudaFuncAttributeMaxDynamicSharedMemorySize, AT_SMEM);

    // side streams + events, created once (no device memory allocation involved)
    static cudaStream_t s1 = nullptr, s2 = nullptr;
    static cudaEvent_t evA = nullptr, evPrep = nullptr, evCpy = nullptr;
    static cudaEvent_t evB[2] = {nullptr, nullptr}, evS[2] = {nullptr, nullptr};
    if (s1 == nullptr) {
        cudaStreamCreateWithFlags(&s1, cudaStreamNonBlocking);
        cudaStreamCreateWithFlags(&s2, cudaStreamNonBlocking);
        cudaEventCreateWithFlags(&evA,    cudaEventDisableTiming);
        cudaEventCreateWithFlags(&evPrep, cudaEventDisableTiming);
        cudaEventCreateWithFlags(&evCpy,  cudaEventDisableTiming);
        cudaEventCreateWithFlags(&evB[0], cudaEventDisableTiming);
        cudaEventCreateWithFlags(&evB[1], cudaEventDisableTiming);
        cudaEventCreateWithFlags(&evS[0], cudaEventDisableTiming);
        cudaEventCreateWithFlags(&evS[1], cudaEventDisableTiming);
    }

    // fork side streams off the (possibly capturing) default stream
    cudaEventRecord(evA, 0);
    cudaStreamWaitEvent(s1, evA, 0);
    cudaStreamWaitEvent(s2, evA, 0);

    // main stream: init + convert (needed by attn scan #0)
    init_kernel<<<(Bb * NQ * D / 4 + 255) / 256, 256>>>(query, pmat, psm, pq16, pqm);
    convert_kernel<<<(Bb * NC * D / 4 + 255) / 256, 256>>>(ctx, pctx16, Bb * NC * D);

    // s1: prep transposes + bias pack (needed from hgemm<1> onward)
    transpose_ctx<<<dim3(D / 32, NC / 32, Bb), dim3(32, 8), 0, s1>>>(ctx, pctxT);
    transpose_weights<<<1856, dim3(32, 8), 0, s1>>>(cw_W, sw_W1, mw_W1, mw_W2, pw16);
    pack_bias<<<(2 * W1N + 255) / 256, 256, 0, s1>>>(mw_b1, sw_b1, ppb);
    cudaEventRecord(evPrep, s1);

    // s2: query -> out_q copy (independent of everything)
    cudaMemcpyAsync(out_q, query, (size_t)Bb * NQ * D * sizeof(float),
                    cudaMemcpyDeviceToDevice, s2);
    cudaEventRecord(evCpy, s2);

    // main: attention scan #0 overlaps with s1/s2 work
    attn_fused<<<Bb, 512, AT_SMEM>>>(pctx16, pqm, psm, pattn16, nullptr);
    cudaStreamWaitEvent(0, evPrep, 0);

    for (int i = 0; i < 2; i++) {
        // d16 = (q - attn@ctx)^2
        hgemm<1><<<dim3(8, 2, Bb), 256, SMEM_BYTES>>>(
            pattn16, pctxT, nullptr, pd16, pq16, nullptr, nullptr,
            NC, NC, D, (size_t)NQ * NC, (size_t)NC * D, (size_t)NQ * D);
        // common = d16 @ cw_W + b (f32)
        hgemm<3><<<dim3(2, 256, 1), 256, SMEM_BYTES>>>(
            pd16, pw16 + W_CW + (size_t)i * AD * D, cw_b + (size_t)i * AD, pcom,
            nullptr, nullptr, nullptr, D, D, AD, 0, 0, 0);
        l2norm256_kernel<<<Bb * NQ / 8, 256>>>(pcom, pcom16);
        // fused W1: [h | sh] = tanh(com16 @ [mw1|sw1] + [b])
        hgemm<4><<<dim3(5, 256, 1), 256, SMEM_BYTES>>>(
            pcom16, pw16 + W_W1 + (size_t)i * W1N * AD, ppb + (size_t)i * W1N, phs16,
            nullptr, nullptr, nullptr, AD, AD, W1N, 0, 0, 0);
        // smooth branch on s1, concurrent with the big mw2 GEMM on main
        cudaEventRecord(evB[i], 0);
        cudaStreamWaitEvent(s1, evB[i], 0);
        sw_reduce_kernel<<<Bb * NQ / 8, 256, 0, s1>>>(
            phs16, sw_W2 + (size_t)i * HD, sw_b2 + i, psm);
        cudaEventRecord(evS[i], s1);
        // matrix update (main)
        hgemm<5><<<dim3(8, 256, 1), 256, SMEM_BYTES>>>(
            phs16, pw16 + W_W2 + (size_t)i * D * MD, mw_b2 + (size_t)i * D, nullptr,
            pq16, pmat, pqm, MD, W1N, D, 0, 0, 0);
        cudaStreamWaitEvent(0, evS[i], 0);
        // next scan (iter i+1 or final)
        attn_fused<<<Bb, 512, AT_SMEM>>>(pctx16, pqm, psm, pattn16,
                                         (i == 1) ? out_attn : nullptr);
    }

    // final wc -> d_out
    hgemm<2><<<dim3(8, 2, Bb), 256, SMEM_BYTES>>>(
        pattn16, pctxT, nullptr, out_wc, nullptr, nullptr, nullptr,
        NC, NC, D, (size_t)NQ * NC, (size_t)NC * D, (size_t)NQ * D);

    // join the copy stream before the launch returns (joins s2 into capture)
    cudaStreamWaitEvent(0, evCpy, 0);
}

// round 15
// speedup vs baseline: 1.1230x; 1.0514x over previous
#include <cuda_runtime.h>
#include <cuda_fp16.h>
#include <stdint.h>
#include <math.h>

// Problem constants
#define Bb 128
#define BH 64     // batches per half-pipeline
#define NQ 256
#define NC 128
#define D  1024
#define AD 256
#define HD 128
#define MD 512
#define W1N 640   // MD + HD fused N

// packed transposed weight offsets (halves)
#define W_CW  0
#define W_W1  (W_CW + 2 * AD * D)
#define W_W2  (W_W1 + 2 * W1N * AD)
#define W_TOT (W_W2 + 2 * D * MD)

// ---------------- scratch (device globals) ----------------
__device__ float  g_smooth[Bb * NQ];
__device__ float  g_common[Bb * NQ * AD];
__device__ float  g_pb[2 * W1N];
__device__ __half g_mat16[Bb * NQ * D];
__device__ __half g_q16[Bb * NQ * D];
__device__ __half g_qm16[Bb * NQ * D];
__device__ __half g_ctx16[Bb * NC * D];
__device__ __half g_ctxT16[Bb * D * NC];
__device__ __half g_attn16[Bb * NQ * NC];
__device__ __half g_d16[Bb * NQ * D];
__device__ __half g_com16[Bb * NQ * AD];
__device__ __half g_hs16[Bb * NQ * W1N];
__device__ __half g_w16[W_TOT];

// ---------------- utils ----------------
__device__ __forceinline__ float warp_sum(float v) {
#pragma unroll
    for (int o = 16; o > 0; o >>= 1) v += __shfl_xor_sync(0xffffffffu, v, o);
    return v;
}

__device__ __forceinline__ uint32_t smem_u32(const void* p) {
    uint32_t a;
    asm("{ .reg .u64 t; cvta.to.shared.u64 t, %1; cvt.u32.u64 %0, t; }" : "=r"(a) : "l"(p));
    return a;
}

__device__ __forceinline__ void cpa16(uint32_t dst, const void* src) {
    asm volatile("cp.async.cg.shared.global [%0], [%1], 16;" :: "r"(dst), "l"(src));
}
#define CPA_COMMIT() asm volatile("cp.async.commit_group;" ::: "memory")
#define CPA_WAIT1()  asm volatile("cp.async.wait_group 1;" ::: "memory")
#define CPA_WAIT0()  asm volatile("cp.async.wait_group 0;" ::: "memory")

__device__ __forceinline__ void ldm4(uint32_t* r, uint32_t a) {
    asm volatile("ldmatrix.sync.aligned.m8n8.x4.shared.b16 {%0,%1,%2,%3}, [%4];"
        : "=r"(r[0]), "=r"(r[1]), "=r"(r[2]), "=r"(r[3]) : "r"(a));
}

__device__ __forceinline__ void mma16(float* c, const uint32_t* a, const uint32_t* b) {
    asm volatile(
        "mma.sync.aligned.m16n8k16.row.col.f32.f16.f16.f32 "
        "{%0,%1,%2,%3},{%4,%5,%6,%7},{%8,%9},{%0,%1,%2,%3};"
        : "+f"(c[0]), "+f"(c[1]), "+f"(c[2]), "+f"(c[3])
        : "r"(a[0]), "r"(a[1]), "r"(a[2]), "r"(a[3]), "r"(b[0]), "r"(b[1]));
}

// epilogue helper
template<int EPI>
__device__ __forceinline__ void epi_store(
    float v0, float v1, size_t o, int n,
    const float* bias, void* Cout,
    const __half* q16, __half* mat16, __half* qm16)
{
    if (EPI == 1) {
        __half2 q2 = *(const __half2*)(q16 + o);
        float t0 = __half2float(__low2half(q2)) - v0;
        float t1 = __half2float(__high2half(q2)) - v1;
        *(__half2*)((__half*)Cout + o) = __floats2half2_rn(t0 * t0, t1 * t1);
    } else if (EPI == 2) {
        float2 w = {v0, v1};
        *(float2*)((float*)Cout + o) = w;
    } else if (EPI == 3) {
        float2 w = {v0 + __ldg(bias + n), v1 + __ldg(bias + n + 1)};
        *(float2*)((float*)Cout + o) = w;
    } else if (EPI == 4) {
        *(__half2*)((__half*)Cout + o) =
            __floats2half2_rn(tanhf(v0 + __ldg(bias + n)),
                              tanhf(v1 + __ldg(bias + n + 1)));
    } else {
        __half2 old2 = *(__half2*)(mat16 + o);
        __half2 q2 = *(const __half2*)(q16 + o);
        float n0v = fminf(1.0f, fmaxf(-1.0f,
            tanhf(v0 + __ldg(bias + n)) + __half2float(__low2half(old2))));
        float n1v = fminf(1.0f, fmaxf(-1.0f,
            tanhf(v1 + __ldg(bias + n + 1)) + __half2float(__high2half(old2))));
        *(__half2*)(mat16 + o) = __floats2half2_rn(n0v, n1v);
        *(__half2*)(qm16 + o) = __floats2half2_rn(
            __half2float(__low2half(q2)) * n0v,
            __half2float(__high2half(q2)) * n1v);
    }
}

// ====== GEMM: 128x128 tile, 256 thr, warp tile 32x64, 2 CTA/SM ======
#define STAGE_BYTES 32768
#define SMEM_BYTES  (3 * STAGE_BYTES)
template<int EPI>
__global__ void __launch_bounds__(256, 2) hgemm(
    const __half* __restrict__ A, const __half* __restrict__ Bw,
    const float* __restrict__ bias, void* __restrict__ Cout,
    const __half* __restrict__ q16, __half* __restrict__ mat16,
    __half* __restrict__ qm16,
    int K, int lda, int ldc, size_t sA, size_t sB, size_t sC)
{
    extern __shared__ __half smemh[];
    const uint32_t sbase = smem_u32(smemh);

    const int tid = threadIdx.x;
    const int lane = tid & 31, warp = tid >> 5;
    const int wm = (warp & 3) * 32, wn = (warp >> 2) * 64;
    const int z = blockIdx.z;
    const int m0 = blockIdx.y * 128, n0 = blockIdx.x * 128;

    const __half* Ab = A + (size_t)z * sA;
    const __half* Bp = Bw + (size_t)z * sB;

    const int ar = tid & 127, acb = (tid >> 7) * 4;
    const int NCH = K >> 6;

    float acc[2][8][4];
#pragma unroll
    for (int i = 0; i < 2; i++)
#pragma unroll
        for (int j = 0; j < 8; j++)
#pragma unroll
            for (int r = 0; r < 4; r++) acc[i][j][r] = 0.0f;

    auto load_chunk = [&](int stage, int ch) {
        const uint32_t Abase = sbase + stage * STAGE_BYTES;
        const uint32_t Bbase = Abase + 16384;
        const __half* ga = Ab + (size_t)(m0 + ar) * lda + ch * 64 + acb * 8;
        const __half* gb = Bp + (size_t)(n0 + ar) * K + ch * 64 + acb * 8;
#pragma unroll
        for (int j = 0; j < 4; j++) {
            int c = acb + j;
            uint32_t sw = ((uint32_t)(c ^ (ar & 7))) << 4;
            cpa16(Abase + ar * 128 + sw, ga + j * 8);
            cpa16(Bbase + ar * 128 + sw, gb + j * 8);
        }
    };

    auto compute = [&](int stage) {
        const uint32_t Abase = sbase + stage * STAGE_BYTES;
        const uint32_t Bbase = Abase + 16384;

        uint32_t aF[2][2][4];
        uint32_t bF[2][4][4];
        {
            const int c = (lane >> 4);
#pragma unroll
            for (int mi = 0; mi < 2; mi++) {
                int row = wm + mi * 16 + (lane & 15);
                ldm4(aF[0][mi], Abase + row * 128 + (((uint32_t)(c ^ (row & 7))) << 4));
            }
#pragma unroll
            for (int nb = 0; nb < 4; nb++) {
                int row = wn + nb * 16 + (lane & 15);
                ldm4(bF[0][nb], Bbase + row * 128 + (((uint32_t)(c ^ (row & 7))) << 4));
            }
        }

#pragma unroll
        for (int s16 = 0; s16 < 4; s16++) {
            const int cur = s16 & 1, nxt = cur ^ 1;
            if (s16 < 3) {
                const int c = (s16 + 1) * 2 + (lane >> 4);
#pragma unroll
                for (int mi = 0; mi < 2; mi++) {
                    int row = wm + mi * 16 + (lane & 15);
                    ldm4(aF[nxt][mi], Abase + row * 128 + (((uint32_t)(c ^ (row & 7))) << 4));
                }
#pragma unroll
                for (int nb = 0; nb < 4; nb++) {
                    int row = wn + nb * 16 + (lane & 15);
                    ldm4(bF[nxt][nb], Bbase + row * 128 + (((uint32_t)(c ^ (row & 7))) << 4));
                }
            }
#pragma unroll
            for (int mi = 0; mi < 2; mi++)
#pragma unroll
                for (int nb = 0; nb < 4; nb++) {
                    uint32_t b0[2] = {bF[cur][nb][0], bF[cur][nb][2]};
                    uint32_t b1[2] = {bF[cur][nb][1], bF[cur][nb][3]};
                    mma16(acc[mi][2 * nb], aF[cur][mi], b0);
                    mma16(acc[mi][2 * nb + 1], aF[cur][mi], b1);
                }
        }
    };

    load_chunk(0, 0);
    CPA_COMMIT();
    if (NCH > 1) { load_chunk(1, 1); CPA_COMMIT(); }

    for (int i = 0; i < NCH; i++) {
        if (i + 2 < NCH) { CPA_WAIT1(); } else { CPA_WAIT0(); }
        __syncthreads();
        if (i + 2 < NCH) {
            load_chunk((i + 2) % 3, i + 2);
            CPA_COMMIT();
        }
        compute(i % 3);
    }

    const int g = lane >> 2, tg = lane & 3;
#pragma unroll
    for (int mi = 0; mi < 2; mi++) {
#pragma unroll
        for (int ni = 0; ni < 8; ni++) {
            int n = n0 + wn + ni * 8 + 2 * tg;
#pragma unroll
            for (int hh = 0; hh < 2; hh++) {
                int m = m0 + wm + mi * 16 + g + hh * 8;
                size_t o = (size_t)z * sC + (size_t)m * ldc + n;
                epi_store<EPI>(acc[mi][ni][hh * 2], acc[mi][ni][hh * 2 + 1],
                               o, n, bias, Cout, q16, mat16, qm16);
            }
        }
    }
}

// ---------------- fused attention scan (unchanged) ----------------
#define AT_STAGE   49152
#define AT_SMSTR   257
#define AT_SMEM    (3 * AT_STAGE)
__global__ void __launch_bounds__(512, 1) attn_fused(
    const __half* __restrict__ ctx16, const __half* __restrict__ qm16,
    const float* __restrict__ smooth,
    __half* __restrict__ a16, float* __restrict__ a32)
{
    extern __shared__ __half smemh[];
    const uint32_t sbase = smem_u32(smemh);
    float* smf = (float*)smemh;
    float* sinv = smf + NC * AT_SMSTR;

    const int tid = threadIdx.x;
    const int lane = tid & 31, warp = tid >> 5;
    const int wm = (warp & 3) * 32, wn = (warp >> 2) * 64;
    const int b = blockIdx.x;

    const __half* Ab = ctx16 + (size_t)b * NC * D;
    const __half* Bp = qm16 + (size_t)b * NQ * D;

    const int arow = tid >> 2, ac0 = (tid & 3) * 2;
    const int brow = tid >> 1, bc0 = (tid & 1) * 4;

    float acc[2][8][4];
#pragma unroll
    for (int i = 0; i < 2; i++)
#pragma unroll
        for (int j = 0; j < 8; j++)
#pragma unroll
            for (int r = 0; r < 4; r++) acc[i][j][r] = 0.0f;

    auto load_chunk = [&](int stage, int ch) {
        const uint32_t Abase = sbase + stage * AT_STAGE;
        const uint32_t Bbase = Abase + 16384;
        const __half* ga = Ab + (size_t)arow * D + ch * 64 + ac0 * 8;
#pragma unroll
        for (int j = 0; j < 2; j++) {
            int c = ac0 + j;
            cpa16(Abase + arow * 128 + (((uint32_t)(c ^ (arow & 7))) << 4), ga + j * 8);
        }
        const __half* gb = Bp + (size_t)brow * D + ch * 64 + bc0 * 8;
#pragma unroll
        for (int j = 0; j < 4; j++) {
            int c = bc0 + j;
            cpa16(Bbase + brow * 128 + (((uint32_t)(c ^ (brow & 7))) << 4), gb + j * 8);
        }
    };

    auto compute = [&](int stage) {
        const uint32_t Abase = sbase + stage * AT_STAGE;
        const uint32_t Bbase = Abase + 16384;
#pragma unroll
        for (int s16 = 0; s16 < 4; s16++) {
            uint32_t a[2][4];
#pragma unroll
            for (int mi = 0; mi < 2; mi++) {
                int row = wm + mi * 16 + (lane & 15);
                int c = s16 * 2 + (lane >> 4);
                ldm4(a[mi], Abase + row * 128 + (((uint32_t)(c ^ (row & 7))) << 4));
            }
            uint32_t bf[4][4];
#pragma unroll
            for (int nb = 0; nb < 4; nb++) {
                int row = wn + nb * 16 + (lane & 15);
                int c = s16 * 2 + (lane >> 4);
                ldm4(bf[nb], Bbase + row * 128 + (((uint32_t)(c ^ (row & 7))) << 4));
            }
#pragma unroll
            for (int mi = 0; mi < 2; mi++)
#pragma unroll
                for (int nb = 0; nb < 4; nb++) {
                    uint32_t b0[2] = {bf[nb][0], bf[nb][2]};
                    uint32_t b1[2] = {bf[nb][1], bf[nb][3]};
                    mma16(acc[mi][2 * nb], a[mi], b0);
                    mma16(acc[mi][2 * nb + 1], a[mi], b1);
                }
        }
    };

    const int NCH = D >> 6;
    load_chunk(0, 0);
    CPA_COMMIT();
    load_chunk(1, 1);
    CPA_COMMIT();
    for (int i = 0; i < NCH; i++) {
        if (i + 2 < NCH) { CPA_WAIT1(); } else { CPA_WAIT0(); }
        __syncthreads();
        if (i + 2 < NCH) {
            load_chunk((i + 2) % 3, i + 2);
            CPA_COMMIT();
        }
        compute(i % 3);
    }

    __syncthreads();
    const int g = lane >> 2, tg = lane & 3;
#pragma unroll
    for (int mi = 0; mi < 2; mi++) {
#pragma unroll
        for (int ni = 0; ni < 8; ni++) {
            int n = wn + ni * 8 + 2 * tg;
#pragma unroll
            for (int hh = 0; hh < 2; hh++) {
                int m = wm + mi * 16 + g + hh * 8;
                float v0 = acc[mi][ni][hh * 2 + 0];
                float v1 = acc[mi][ni][hh * 2 + 1];
                smf[m * AT_SMSTR + n]     = (v0 >= 0.0f) ? v0 : 0.1f * v0;
                smf[m * AT_SMSTR + n + 1] = (v1 >= 0.0f) ? v1 : 0.1f * v1;
            }
        }
    }
    __syncthreads();

#pragma unroll
    for (int r = 0; r < 8; r++) {
        int c = warp * 8 + r;
        const float* p = smf + c * AT_SMSTR;
        float s = 0.0f;
#pragma unroll
        for (int j = 0; j < 8; j++) {
            float x = p[lane + 32 * j];
            s += x * x;
        }
        s = warp_sum(s);
        if (lane == 0) sinv[c] = 1.0f / (sqrtf(s) + 1e-8f);
    }
    __syncthreads();

    for (int qi = warp; qi < NQ; qi += 16) {
        float sf = smooth[b * NQ + qi];
        float v0 = smf[(lane)      * AT_SMSTR + qi] * sinv[lane]      * sf;
        float v1 = smf[(lane + 32) * AT_SMSTR + qi] * sinv[lane + 32] * sf;
        float v2 = smf[(lane + 64) * AT_SMSTR + qi] * sinv[lane + 64] * sf;
        float v3 = smf[(lane + 96) * AT_SMSTR + qi] * sinv[lane + 96] * sf;
        float mx = fmaxf(fmaxf(v0, v1), fmaxf(v2, v3));
#pragma unroll
        for (int o = 16; o > 0; o >>= 1) mx = fmaxf(mx, __shfl_xor_sync(0xffffffffu, mx, o));
        float e0 = expf(v0 - mx), e1 = expf(v1 - mx), e2 = expf(v2 - mx), e3 = expf(v3 - mx);
        float s = warp_sum(e0 + e1 + e2 + e3);
        float inv = 1.0f / s;
        size_t base = ((size_t)b * NQ + qi) * NC;
        a16[base + lane]      = __float2half_rn(e0 * inv);
        a16[base + lane + 32] = __float2half_rn(e1 * inv);
        a16[base + lane + 64] = __float2half_rn(e2 * inv);
        a16[base + lane + 96] = __float2half_rn(e3 * inv);
        if (a32) {
            a32[base + lane]      = e0 * inv;
            a32[base + lane + 32] = e1 * inv;
            a32[base + lane + 64] = e2 * inv;
            a32[base + lane + 96] = e3 * inv;
        }
    }
}

// ---------------- transposes ----------------
__device__ __forceinline__ void tr_tile(const float* s, __half* d, int R, int C,
                                        int bx, int by) {
    __shared__ float t[32][33];
    int r0 = by * 32, c0 = bx * 32;
    for (int j = threadIdx.y; j < 32; j += 8)
        t[j][threadIdx.x] = s[(size_t)(r0 + j) * C + c0 + threadIdx.x];
    __syncthreads();
    for (int j = threadIdx.y; j < 32; j += 8)
        d[(size_t)(c0 + j) * R + r0 + threadIdx.x] = __float2half_rn(t[threadIdx.x][j]);
}

__global__ void transpose_ctx(const float* __restrict__ ctx, __half* __restrict__ dst) {
    const float* s = ctx + (size_t)blockIdx.z * NC * D;
    __half* d = dst + (size_t)blockIdx.z * NC * D;
    tr_tile(s, d, NC, D, blockIdx.x, blockIdx.y);
}

__global__ void transpose_weights(const float* __restrict__ cw, const float* __restrict__ sw1,
                                  const float* __restrict__ mw1, const float* __restrict__ mw2,
                                  __half* __restrict__ w16) {
    int blk = blockIdx.x;
    const float* src; __half* dst; int R, C;
    if (blk < 512) {
        int l = blk >> 8; blk &= 255;
        src = cw + (size_t)l * D * AD; dst = w16 + W_CW + (size_t)l * AD * D;
        R = D; C = AD;
    } else if (blk < 576) {
        blk -= 512; int l = blk >> 5; blk &= 31;
        src = sw1 + (size_t)l * AD * HD; dst = w16 + W_W1 + (size_t)l * W1N * AD + 512 * AD;
        R = AD; C = HD;
    } else if (blk < 832) {
        blk -= 576; int l = blk >> 7; blk &= 127;
        src = mw1 + (size_t)l * AD * MD; dst = w16 + W_W1 + (size_t)l * W1N * AD;
        R = AD; C = MD;
    } else {
        blk -= 832; int l = blk >> 9; blk &= 511;
        src = mw2 + (size_t)l * MD * D; dst = w16 + W_W2 + (size_t)l * D * MD;
        R = MD; C = D;
    }
    int bx = blk % (C / 32), by = blk / (C / 32);
    tr_tile(src, dst, R, C, bx, by);
}

__global__ void pack_bias(const float* __restrict__ mw_b1, const float* __restrict__ sw_b1,
                          float* __restrict__ pb) {
    int i = blockIdx.x * blockDim.x + threadIdx.x;
    if (i < 2 * W1N) {
        int l = i / W1N, n = i % W1N;
        pb[i] = (n < MD) ? mw_b1[l * MD + n] : sw_b1[l * HD + n - MD];
    }
}

// ---------------- elementwise kernels ----------------
__global__ void init_kernel(const float* __restrict__ query,
                            __half* __restrict__ mat16, float* __restrict__ smooth,
                            __half* __restrict__ q16, __half* __restrict__ qm16,
                            size_t nbig, size_t nsm) {
    size_t i = ((size_t)blockIdx.x * blockDim.x + threadIdx.x) * 4;
    if (i < nbig) {
        float4 q = *(const float4*)(query + i);
        __half2 h0 = __floats2half2_rn(q.x, q.y);
        __half2 h1 = __floats2half2_rn(q.z, q.w);
        __half2 one2 = __floats2half2_rn(1.0f, 1.0f);
        *(__half2*)(q16 + i)      = h0;
        *(__half2*)(q16 + i + 2)  = h1;
        *(__half2*)(qm16 + i)     = h0;
        *(__half2*)(qm16 + i + 2) = h1;
        *(__half2*)(mat16 + i)     = one2;
        *(__half2*)(mat16 + i + 2) = one2;
    }
    if (i / 4 < nsm) smooth[i / 4] = 10.0f;
}

__global__ void convert_kernel(const float* __restrict__ src, __half* __restrict__ dst, int n) {
    int i = (blockIdx.x * blockDim.x + threadIdx.x) * 4;
    if (i < n) {
        float4 v = *(const float4*)(src + i);
        *(__half2*)(dst + i)     = __floats2half2_rn(v.x, v.y);
        *(__half2*)(dst + i + 2) = __floats2half2_rn(v.z, v.w);
    }
}

__global__ void l2norm256_kernel(const float* __restrict__ X, __half* __restrict__ Y) {
    int row = blockIdx.x * 8 + (threadIdx.x >> 5);
    int lane = threadIdx.x & 31;
    const float* p = X + (size_t)row * AD;
    float vals[8];
    float s = 0.0f;
#pragma unroll
    for (int j = 0; j < 8; j++) {
        vals[j] = p[lane + 32 * j];
        s += vals[j] * vals[j];
    }
    s = warp_sum(s);
    float inv = 1.0f / (sqrtf(s) + 1e-8f);
    __half* y = Y + (size_t)row * AD;
#pragma unroll
    for (int j = 0; j < 8; j++)
        y[lane + 32 * j] = __float2half_rn(vals[j] * inv);
}

__global__ void sw_reduce_kernel(const __half* __restrict__ hs, const float* __restrict__ w2,
                                 const float* __restrict__ b2, float* __restrict__ smooth)
{
    int row = blockIdx.x * 8 + (threadIdx.x >> 5);
    int lane = threadIdx.x & 31;
    const __half* r = hs + (size_t)row * W1N + MD;
    float s = __half2float(r[lane]) * w2[lane]
            + __half2float(r[lane + 32]) * w2[lane + 32]
            + __half2float(r[lane + 64]) * w2[lane + 64]
            + __half2float(r[lane + 96]) * w2[lane + 96];
    s = warp_sum(s);
    if (lane == 0) smooth[row] = fmaxf(0.0f, s + b2[0] + smooth[row]);
}

// ---------------- orchestration: two independent 64-batch pipelines ----------------
extern "C" void kernel_launch(void* const* d_in, const int* in_sizes, int n_in,
                              void* d_out, int out_size)
{
    const float* query = (const float*)d_in[0];
    const float* ctx   = (const float*)d_in[1];
    const float* cw_W  = (const float*)d_in[2];
    const float* cw_b  = (const float*)d_in[3];
    const float* sw_W1 = (const float*)d_in[4];
    const float* sw_b1 = (const float*)d_in[5];
    const float* sw_W2 = (const float*)d_in[6];
    const float* sw_b2 = (const float*)d_in[7];
    const float* mw_W1 = (const float*)d_in[8];
    const float* mw_b1 = (const float*)d_in[9];
    const float* mw_W2 = (const float*)d_in[10];
    const float* mw_b2 = (const float*)d_in[11];

    float* out      = (float*)d_out;
    float* out_q    = out;
    float* out_wc   = out + (size_t)Bb * NQ * D;
    float* out_attn = out + 2 * (size_t)Bb * NQ * D;

    float *psm, *pcom, *ppb;
    __half *pmat, *pq16, *pqm, *pctx16, *pctxT, *pattn16, *pd16, *pcom16, *phs16, *pw16;
    cudaGetSymbolAddress((void**)&psm,     g_smooth);
    cudaGetSymbolAddress((void**)&pcom,    g_common);
    cudaGetSymbolAddress((void**)&ppb,     g_pb);
    cudaGetSymbolAddress((void**)&pmat,    g_mat16);
    cudaGetSymbolAddress((void**)&pq16,    g_q16);
    cudaGetSymbolAddress((void**)&pqm,     g_qm16);
    cudaGetSymbolAddress((void**)&pctx16,  g_ctx16);
    cudaGetSymbolAddress((void**)&pctxT,   g_ctxT16);
    cudaGetSymbolAddress((void**)&pattn16, g_attn16);
    cudaGetSymbolAddress((void**)&pd16,    g_d16);
    cudaGetSymbolAddress((void**)&pcom16,  g_com16);
    cudaGetSymbolAddress((void**)&phs16,   g_hs16);
    cudaGetSymbolAddress((void**)&pw16,    g_w16);

    cudaFuncSetAttribute(hgemm<1>, cudaFuncAttributeMaxDynamicSharedMemorySize, SMEM_BYTES);
    cudaFuncSetAttribute(hgemm<2>, cudaFuncAttributeMaxDynamicSharedMemorySize, SMEM_BYTES);
    cudaFuncSetAttribute(hgemm<3>, cudaFuncAttributeMaxDynamicSharedMemorySize, SMEM_BYTES);
    cudaFuncSetAttribute(hgemm<4>, cudaFuncAttributeMaxDynamicSharedMemorySize, SMEM_BYTES);
    cudaFuncSetAttribute(hgemm<5>, cudaFuncAttributeMaxDynamicSharedMemorySize, SMEM_BYTES);
    cudaFuncSetAttribute(attn_fused, cudaFuncAttributeMaxDynamicSharedMemorySize, AT_SMEM);

    static cudaStream_t s1 = nullptr, s2 = nullptr;
    static cudaEvent_t evA = nullptr, evW = nullptr, evCpy = nullptr, evH1 = nullptr;
    if (s1 == nullptr) {
        cudaStreamCreateWithFlags(&s1, cudaStreamNonBlocking);
        cudaStreamCreateWithFlags(&s2, cudaStreamNonBlocking);
        cudaEventCreateWithFlags(&evA,   cudaEventDisableTiming);
        cudaEventCreateWithFlags(&evW,   cudaEventDisableTiming);
        cudaEventCreateWithFlags(&evCpy, cudaEventDisableTiming);
        cudaEventCreateWithFlags(&evH1,  cudaEventDisableTiming);
    }

    // fork side streams off the capture stream
    cudaEventRecord(evA, 0);
    cudaStreamWaitEvent(s1, evA, 0);
    cudaStreamWaitEvent(s2, evA, 0);

    // s2: shared weights prep + out_q copy
    transpose_weights<<<1856, dim3(32, 8), 0, s2>>>(cw_W, sw_W1, mw_W1, mw_W2, pw16);
    pack_bias<<<(2 * W1N + 255) / 256, 256, 0, s2>>>(mw_b1, sw_b1, ppb);
    cudaEventRecord(evW, s2);
    cudaMemcpyAsync(out_q, query, (size_t)Bb * NQ * D * sizeof(float),
                    cudaMemcpyDeviceToDevice, s2);
    cudaEventRecord(evCpy, s2);

    // per-half pipeline (fully independent per batch-half)
    auto run_half = [&](cudaStream_t st, int h) {
        const size_t oQ  = (size_t)h * BH * NQ * D;    // query-shaped (q16/qm16/mat16/d16/out_wc)
        const size_t oC  = (size_t)h * BH * NC * D;    // ctx-shaped
        const size_t oS  = (size_t)h * BH * NQ;        // smooth
        const size_t oA  = (size_t)h * BH * NQ * NC;   // attn-shaped
        const size_t oCm = (size_t)h * BH * NQ * AD;   // common-shaped
        const size_t oH  = (size_t)h * BH * NQ * W1N;  // hs-shaped

        // per-half prep
        init_kernel<<<(BH * NQ * D / 4 + 255) / 256, 256, 0, st>>>(
            query + oQ, pmat + oQ, psm + oS, pq16 + oQ, pqm + oQ,
            (size_t)BH * NQ * D, (size_t)BH * NQ);
        convert_kernel<<<(BH * NC * D / 4 + 255) / 256, 256, 0, st>>>(
            ctx + oC, pctx16 + oC, BH * NC * D);
        transpose_ctx<<<dim3(D / 32, NC / 32, BH), dim3(32, 8), 0, st>>>(
            ctx + oC, pctxT + oC);

        // scan #0
        attn_fused<<<BH, 512, AT_SMEM, st>>>(pctx16 + oC, pqm + oQ, psm + oS,
                                             pattn16 + oA, nullptr);
        cudaStreamWaitEvent(st, evW, 0);

        for (int i = 0; i < 2; i++) {
            hgemm<1><<<dim3(8, 2, BH), 256, SMEM_BYTES, st>>>(
                pattn16 + oA, pctxT + oC, nullptr, pd16 + oQ, pq16 + oQ, nullptr, nullptr,
                NC, NC, D, (size_t)NQ * NC, (size_t)NC * D, (size_t)NQ * D);
            hgemm<3><<<dim3(2, BH * NQ / 128, 1), 256, SMEM_BYTES, st>>>(
                pd16 + oQ, pw16 + W_CW + (size_t)i * AD * D, cw_b + (size_t)i * AD,
                pcom + oCm, nullptr, nullptr, nullptr, D, D, AD, 0, 0, 0);
            l2norm256_kernel<<<BH * NQ / 8, 256, 0, st>>>(pcom + oCm, pcom16 + oCm);
            hgemm<4><<<dim3(5, BH * NQ / 128, 1), 256, SMEM_BYTES, st>>>(
                pcom16 + oCm, pw16 + W_W1 + (size_t)i * W1N * AD, ppb + (size_t)i * W1N,
                phs16 + oH, nullptr, nullptr, nullptr, AD, AD, W1N, 0, 0, 0);
            sw_reduce_kernel<<<BH * NQ / 8, 256, 0, st>>>(
                phs16 + oH, sw_W2 + (size_t)i * HD, sw_b2 + i, psm + oS);
            hgemm<5><<<dim3(8, BH * NQ / 128, 1), 256, SMEM_BYTES, st>>>(
                phs16 + oH, pw16 + W_W2 + (size_t)i * D * MD, mw_b2 + (size_t)i * D, nullptr,
                pq16 + oQ, pmat + oQ, pqm + oQ, MD, W1N, D, 0, 0, 0);
            attn_fused<<<BH, 512, AT_SMEM, st>>>(
                pctx16 + oC, pqm + oQ, psm + oS, pattn16 + oA,
                (i == 1) ? (out_attn + oA) : nullptr);
        }

        hgemm<2><<<dim3(8, 2, BH), 256, SMEM_BYTES, st>>>(
            pattn16 + oA, pctxT + oC, nullptr, out_wc + oQ, nullptr, nullptr, nullptr,
            NC, NC, D, (size_t)NQ * NC, (size_t)NC * D, (size_t)NQ * D);
    };

    run_half((cudaStream_t)0, 0);   // half 0 on the capture stream
    run_half(s1, 1);                // half 1 on side stream

    // join: capture stream waits for half 1 and the out_q copy
    cudaEventRecord(evH1, s1);
    cudaStreamWaitEvent(0, evH1, 0);
    cudaStreamWaitEvent(0, evCpy, 0);
}

// round 17
// speedup vs baseline: 1.1333x; 1.0091x over previous
#include <cuda_runtime.h>
#include <cuda_fp16.h>
#include <stdint.h>
#include <math.h>

// Problem constants
#define Bb 128
#define BH 64     // batches per half-pipeline
#define NQ 256
#define NC 128
#define D  1024
#define AD 256
#define HD 128
#define MD 512
#define W1N 640   // MD + HD fused N

// packed transposed weight offsets (halves)
#define W_CW  0
#define W_W1  (W_CW + 2 * AD * D)
#define W_W2  (W_W1 + 2 * W1N * AD)
#define W_TOT (W_W2 + 2 * D * MD)

// ---------------- scratch (device globals) ----------------
__device__ float  g_smooth[Bb * NQ];
__device__ float  g_common[Bb * NQ * AD];
__device__ float  g_pb[2 * W1N];
__device__ __half g_mat16[Bb * NQ * D];
__device__ __half g_q16[Bb * NQ * D];
__device__ __half g_qm16[Bb * NQ * D];
__device__ __half g_ctx16[Bb * NC * D];
__device__ __half g_ctxT16[Bb * D * NC];
__device__ __half g_attn16[Bb * NQ * NC];
__device__ __half g_d16[Bb * NQ * D];
__device__ __half g_com16[Bb * NQ * AD];
__device__ __half g_hs16[Bb * NQ * W1N];
__device__ __half g_w16[W_TOT];

// ---------------- utils ----------------
__device__ __forceinline__ float warp_sum(float v) {
#pragma unroll
    for (int o = 16; o > 0; o >>= 1) v += __shfl_xor_sync(0xffffffffu, v, o);
    return v;
}

__device__ __forceinline__ uint32_t smem_u32(const void* p) {
    uint32_t a;
    asm("{ .reg .u64 t; cvta.to.shared.u64 t, %1; cvt.u32.u64 %0, t; }" : "=r"(a) : "l"(p));
    return a;
}

__device__ __forceinline__ void cpa16(uint32_t dst, const void* src) {
    asm volatile("cp.async.cg.shared.global [%0], [%1], 16;" :: "r"(dst), "l"(src));
}
#define CPA_COMMIT() asm volatile("cp.async.commit_group;" ::: "memory")
#define CPA_WAIT1()  asm volatile("cp.async.wait_group 1;" ::: "memory")
#define CPA_WAIT0()  asm volatile("cp.async.wait_group 0;" ::: "memory")

__device__ __forceinline__ void ldm4(uint32_t* r, uint32_t a) {
    asm volatile("ldmatrix.sync.aligned.m8n8.x4.shared.b16 {%0,%1,%2,%3}, [%4];"
        : "=r"(r[0]), "=r"(r[1]), "=r"(r[2]), "=r"(r[3]) : "r"(a));
}

__device__ __forceinline__ void mma16(float* c, const uint32_t* a, const uint32_t* b) {
    asm volatile(
        "mma.sync.aligned.m16n8k16.row.col.f32.f16.f16.f32 "
        "{%0,%1,%2,%3},{%4,%5,%6,%7},{%8,%9},{%0,%1,%2,%3};"
        : "+f"(c[0]), "+f"(c[1]), "+f"(c[2]), "+f"(c[3])
        : "r"(a[0]), "r"(a[1]), "r"(a[2]), "r"(a[3]), "r"(b[0]), "r"(b[1]));
}

// epilogue helper
template<int EPI>
__device__ __forceinline__ void epi_store(
    float v0, float v1, size_t o, int n,
    const float* bias, void* Cout,
    const __half* q16, __half* mat16, __half* qm16)
{
    if (EPI == 1) {
        __half2 q2 = *(const __half2*)(q16 + o);
        float t0 = __half2float(__low2half(q2)) - v0;
        float t1 = __half2float(__high2half(q2)) - v1;
        *(__half2*)((__half*)Cout + o) = __floats2half2_rn(t0 * t0, t1 * t1);
    } else if (EPI == 2) {
        float2 w = {v0, v1};
        *(float2*)((float*)Cout + o) = w;
    } else if (EPI == 3) {
        float2 w = {v0 + __ldg(bias + n), v1 + __ldg(bias + n + 1)};
        *(float2*)((float*)Cout + o) = w;
    } else if (EPI == 4) {
        *(__half2*)((__half*)Cout + o) =
            __floats2half2_rn(tanhf(v0 + __ldg(bias + n)),
                              tanhf(v1 + __ldg(bias + n + 1)));
    } else {
        __half2 old2 = *(__half2*)(mat16 + o);
        __half2 q2 = *(const __half2*)(q16 + o);
        float n0v = fminf(1.0f, fmaxf(-1.0f,
            tanhf(v0 + __ldg(bias + n)) + __half2float(__low2half(old2))));
        float n1v = fminf(1.0f, fmaxf(-1.0f,
            tanhf(v1 + __ldg(bias + n + 1)) + __half2float(__high2half(old2))));
        *(__half2*)(mat16 + o) = __floats2half2_rn(n0v, n1v);
        *(__half2*)(qm16 + o) = __floats2half2_rn(
            __half2float(__low2half(q2)) * n0v,
            __half2float(__high2half(q2)) * n1v);
    }
}

// ====== GEMM: 128x128 tile, 256 thr, warp tile 32x64, 2 CTA/SM ======
#define STAGE_BYTES 32768
#define SMEM_BYTES  (3 * STAGE_BYTES)
template<int EPI>
__global__ void __launch_bounds__(256, 2) hgemm(
    const __half* __restrict__ A, const __half* __restrict__ Bw,
    const float* __restrict__ bias, void* __restrict__ Cout,
    const __half* __restrict__ q16, __half* __restrict__ mat16,
    __half* __restrict__ qm16,
    int K, int lda, int ldc, size_t sA, size_t sB, size_t sC)
{
    extern __shared__ __half smemh[];
    const uint32_t sbase = smem_u32(smemh);

    const int tid = threadIdx.x;
    const int lane = tid & 31, warp = tid >> 5;
    const int wm = (warp & 3) * 32, wn = (warp >> 2) * 64;
    const int z = blockIdx.z;
    const int m0 = blockIdx.y * 128, n0 = blockIdx.x * 128;

    const __half* Ab = A + (size_t)z * sA;
    const __half* Bp = Bw + (size_t)z * sB;

    const int ar = tid & 127, acb = (tid >> 7) * 4;
    const int NCH = K >> 6;

    float acc[2][8][4];
#pragma unroll
    for (int i = 0; i < 2; i++)
#pragma unroll
        for (int j = 0; j < 8; j++)
#pragma unroll
            for (int r = 0; r < 4; r++) acc[i][j][r] = 0.0f;

    auto load_chunk = [&](int stage, int ch) {
        const uint32_t Abase = sbase + stage * STAGE_BYTES;
        const uint32_t Bbase = Abase + 16384;
        const __half* ga = Ab + (size_t)(m0 + ar) * lda + ch * 64 + acb * 8;
        const __half* gb = Bp + (size_t)(n0 + ar) * K + ch * 64 + acb * 8;
#pragma unroll
        for (int j = 0; j < 4; j++) {
            int c = acb + j;
            uint32_t sw = ((uint32_t)(c ^ (ar & 7))) << 4;
            cpa16(Abase + ar * 128 + sw, ga + j * 8);
            cpa16(Bbase + ar * 128 + sw, gb + j * 8);
        }
    };

    auto compute = [&](int stage) {
        const uint32_t Abase = sbase + stage * STAGE_BYTES;
        const uint32_t Bbase = Abase + 16384;

        uint32_t aF[2][2][4];
        uint32_t bF[2][4][4];
        {
            const int c = (lane >> 4);
#pragma unroll
            for (int mi = 0; mi < 2; mi++) {
                int row = wm + mi * 16 + (lane & 15);
                ldm4(aF[0][mi], Abase + row * 128 + (((uint32_t)(c ^ (row & 7))) << 4));
            }
#pragma unroll
            for (int nb = 0; nb < 4; nb++) {
                int row = wn + nb * 16 + (lane & 15);
                ldm4(bF[0][nb], Bbase + row * 128 + (((uint32_t)(c ^ (row & 7))) << 4));
            }
        }

#pragma unroll
        for (int s16 = 0; s16 < 4; s16++) {
            const int cur = s16 & 1, nxt = cur ^ 1;
            if (s16 < 3) {
                const int c = (s16 + 1) * 2 + (lane >> 4);
#pragma unroll
                for (int mi = 0; mi < 2; mi++) {
                    int row = wm + mi * 16 + (lane & 15);
                    ldm4(aF[nxt][mi], Abase + row * 128 + (((uint32_t)(c ^ (row & 7))) << 4));
                }
#pragma unroll
                for (int nb = 0; nb < 4; nb++) {
                    int row = wn + nb * 16 + (lane & 15);
                    ldm4(bF[nxt][nb], Bbase + row * 128 + (((uint32_t)(c ^ (row & 7))) << 4));
                }
            }
#pragma unroll
            for (int mi = 0; mi < 2; mi++)
#pragma unroll
                for (int nb = 0; nb < 4; nb++) {
                    uint32_t b0[2] = {bF[cur][nb][0], bF[cur][nb][2]};
                    uint32_t b1[2] = {bF[cur][nb][1], bF[cur][nb][3]};
                    mma16(acc[mi][2 * nb], aF[cur][mi], b0);
                    mma16(acc[mi][2 * nb + 1], aF[cur][mi], b1);
                }
        }
    };

    load_chunk(0, 0);
    CPA_COMMIT();
    if (NCH > 1) { load_chunk(1, 1); CPA_COMMIT(); }

    for (int i = 0; i < NCH; i++) {
        if (i + 2 < NCH) { CPA_WAIT1(); } else { CPA_WAIT0(); }
        __syncthreads();
        if (i + 2 < NCH) {
            load_chunk((i + 2) % 3, i + 2);
            CPA_COMMIT();
        }
        compute(i % 3);
    }

    const int g = lane >> 2, tg = lane & 3;
#pragma unroll
    for (int mi = 0; mi < 2; mi++) {
#pragma unroll
        for (int ni = 0; ni < 8; ni++) {
            int n = n0 + wn + ni * 8 + 2 * tg;
#pragma unroll
            for (int hh = 0; hh < 2; hh++) {
                int m = m0 + wm + mi * 16 + g + hh * 8;
                size_t o = (size_t)z * sC + (size_t)m * ldc + n;
                epi_store<EPI>(acc[mi][ni][hh * 2], acc[mi][ni][hh * 2 + 1],
                               o, n, bias, Cout, q16, mat16, qm16);
            }
        }
    }
}

// ---------------- fused attention scan ----------------
#define AT_STAGE   49152
#define AT_SMSTR   257
#define AT_SMEM    (3 * AT_STAGE)
__global__ void __launch_bounds__(512, 1) attn_fused(
    const __half* __restrict__ ctx16, const __half* __restrict__ qm16,
    const float* __restrict__ smooth,
    __half* __restrict__ a16, float* __restrict__ a32)
{
    extern __shared__ __half smemh[];
    const uint32_t sbase = smem_u32(smemh);
    float* smf = (float*)smemh;
    float* sinv = smf + NC * AT_SMSTR;

    const int tid = threadIdx.x;
    const int lane = tid & 31, warp = tid >> 5;
    const int wm = (warp & 3) * 32, wn = (warp >> 2) * 64;
    const int b = blockIdx.x;

    const __half* Ab = ctx16 + (size_t)b * NC * D;
    const __half* Bp = qm16 + (size_t)b * NQ * D;

    const int arow = tid >> 2, ac0 = (tid & 3) * 2;
    const int brow = tid >> 1, bc0 = (tid & 1) * 4;

    float acc[2][8][4];
#pragma unroll
    for (int i = 0; i < 2; i++)
#pragma unroll
        for (int j = 0; j < 8; j++)
#pragma unroll
            for (int r = 0; r < 4; r++) acc[i][j][r] = 0.0f;

    auto load_chunk = [&](int stage, int ch) {
        const uint32_t Abase = sbase + stage * AT_STAGE;
        const uint32_t Bbase = Abase + 16384;
        const __half* ga = Ab + (size_t)arow * D + ch * 64 + ac0 * 8;
#pragma unroll
        for (int j = 0; j < 2; j++) {
            int c = ac0 + j;
            cpa16(Abase + arow * 128 + (((uint32_t)(c ^ (arow & 7))) << 4), ga + j * 8);
        }
        const __half* gb = Bp + (size_t)brow * D + ch * 64 + bc0 * 8;
#pragma unroll
        for (int j = 0; j < 4; j++) {
            int c = bc0 + j;
            cpa16(Bbase + brow * 128 + (((uint32_t)(c ^ (brow & 7))) << 4), gb + j * 8);
        }
    };

    auto compute = [&](int stage) {
        const uint32_t Abase = sbase + stage * AT_STAGE;
        const uint32_t Bbase = Abase + 16384;
#pragma unroll
        for (int s16 = 0; s16 < 4; s16++) {
            uint32_t a[2][4];
#pragma unroll
            for (int mi = 0; mi < 2; mi++) {
                int row = wm + mi * 16 + (lane & 15);
                int c = s16 * 2 + (lane >> 4);
                ldm4(a[mi], Abase + row * 128 + (((uint32_t)(c ^ (row & 7))) << 4));
            }
            uint32_t bf[4][4];
#pragma unroll
            for (int nb = 0; nb < 4; nb++) {
                int row = wn + nb * 16 + (lane & 15);
                int c = s16 * 2 + (lane >> 4);
                ldm4(bf[nb], Bbase + row * 128 + (((uint32_t)(c ^ (row & 7))) << 4));
            }
#pragma unroll
            for (int mi = 0; mi < 2; mi++)
#pragma unroll
                for (int nb = 0; nb < 4; nb++) {
                    uint32_t b0[2] = {bf[nb][0], bf[nb][2]};
                    uint32_t b1[2] = {bf[nb][1], bf[nb][3]};
                    mma16(acc[mi][2 * nb], a[mi], b0);
                    mma16(acc[mi][2 * nb + 1], a[mi], b1);
                }
        }
    };

    const int NCH = D >> 6;
    load_chunk(0, 0);
    CPA_COMMIT();
    load_chunk(1, 1);
    CPA_COMMIT();
    for (int i = 0; i < NCH; i++) {
        if (i + 2 < NCH) { CPA_WAIT1(); } else { CPA_WAIT0(); }
        __syncthreads();
        if (i + 2 < NCH) {
            load_chunk((i + 2) % 3, i + 2);
            CPA_COMMIT();
        }
        compute(i % 3);
    }

    __syncthreads();
    const int g = lane >> 2, tg = lane & 3;
#pragma unroll
    for (int mi = 0; mi < 2; mi++) {
#pragma unroll
        for (int ni = 0; ni < 8; ni++) {
            int n = wn + ni * 8 + 2 * tg;
#pragma unroll
            for (int hh = 0; hh < 2; hh++) {
                int m = wm + mi * 16 + g + hh * 8;
                float v0 = acc[mi][ni][hh * 2 + 0];
                float v1 = acc[mi][ni][hh * 2 + 1];
                smf[m * AT_SMSTR + n]     = (v0 >= 0.0f) ? v0 : 0.1f * v0;
                smf[m * AT_SMSTR + n + 1] = (v1 >= 0.0f) ? v1 : 0.1f * v1;
            }
        }
    }
    __syncthreads();

#pragma unroll
    for (int r = 0; r < 8; r++) {
        int c = warp * 8 + r;
        const float* p = smf + c * AT_SMSTR;
        float s = 0.0f;
#pragma unroll
        for (int j = 0; j < 8; j++) {
            float x = p[lane + 32 * j];
            s += x * x;
        }
        s = warp_sum(s);
        if (lane == 0) sinv[c] = 1.0f / (sqrtf(s) + 1e-8f);
    }
    __syncthreads();

    for (int qi = warp; qi < NQ; qi += 16) {
        float sf = smooth[b * NQ + qi];
        float v0 = smf[(lane)      * AT_SMSTR + qi] * sinv[lane]      * sf;
        float v1 = smf[(lane + 32) * AT_SMSTR + qi] * sinv[lane + 32] * sf;
        float v2 = smf[(lane + 64) * AT_SMSTR + qi] * sinv[lane + 64] * sf;
        float v3 = smf[(lane + 96) * AT_SMSTR + qi] * sinv[lane + 96] * sf;
        float mx = fmaxf(fmaxf(v0, v1), fmaxf(v2, v3));
#pragma unroll
        for (int o = 16; o > 0; o >>= 1) mx = fmaxf(mx, __shfl_xor_sync(0xffffffffu, mx, o));
        float e0 = expf(v0 - mx), e1 = expf(v1 - mx), e2 = expf(v2 - mx), e3 = expf(v3 - mx);
        float s = warp_sum(e0 + e1 + e2 + e3);
        float inv = 1.0f / s;
        size_t base = ((size_t)b * NQ + qi) * NC;
        a16[base + lane]      = __float2half_rn(e0 * inv);
        a16[base + lane + 32] = __float2half_rn(e1 * inv);
        a16[base + lane + 64] = __float2half_rn(e2 * inv);
        a16[base + lane + 96] = __float2half_rn(e3 * inv);
        if (a32) {
            a32[base + lane]      = e0 * inv;
            a32[base + lane + 32] = e1 * inv;
            a32[base + lane + 64] = e2 * inv;
            a32[base + lane + 96] = e3 * inv;
        }
    }
}

// ---------------- fused ctx prep: f32 [c][d] -> f16 [c][d] AND f16 [d][c] ----
__global__ void ctx_prep(const float* __restrict__ ctx, __half* __restrict__ c16,
                         __half* __restrict__ cT) {
    __shared__ float t[32][33];
    const float* s = ctx + (size_t)blockIdx.z * NC * D;
    __half* d16p = c16 + (size_t)blockIdx.z * NC * D;
    __half* dT   = cT  + (size_t)blockIdx.z * NC * D;
    int r0 = blockIdx.y * 32, c0 = blockIdx.x * 32;
    for (int j = threadIdx.y; j < 32; j += 8) {
        float v = s[(size_t)(r0 + j) * D + c0 + threadIdx.x];
        t[j][threadIdx.x] = v;
        d16p[(size_t)(r0 + j) * D + c0 + threadIdx.x] = __float2half_rn(v);
    }
    __syncthreads();
    for (int j = threadIdx.y; j < 32; j += 8)
        dT[(size_t)(c0 + j) * NC + r0 + threadIdx.x] = __float2half_rn(t[threadIdx.x][j]);
}

// ---------------- transposes ----------------
__device__ __forceinline__ void tr_tile(const float* s, __half* d, int R, int C,
                                        int bx, int by) {
    __shared__ float t[32][33];
    int r0 = by * 32, c0 = bx * 32;
    for (int j = threadIdx.y; j < 32; j += 8)
        t[j][threadIdx.x] = s[(size_t)(r0 + j) * C + c0 + threadIdx.x];
    __syncthreads();
    for (int j = threadIdx.y; j < 32; j += 8)
        d[(size_t)(c0 + j) * R + r0 + threadIdx.x] = __float2half_rn(t[threadIdx.x][j]);
}

__global__ void transpose_weights(const float* __restrict__ cw, const float* __restrict__ sw1,
                                  const float* __restrict__ mw1, const float* __restrict__ mw2,
                                  __half* __restrict__ w16) {
    int blk = blockIdx.x;
    const float* src; __half* dst; int R, C;
    if (blk < 512) {
        int l = blk >> 8; blk &= 255;
        src = cw + (size_t)l * D * AD; dst = w16 + W_CW + (size_t)l * AD * D;
        R = D; C = AD;
    } else if (blk < 576) {
        blk -= 512; int l = blk >> 5; blk &= 31;
        src = sw1 + (size_t)l * AD * HD; dst = w16 + W_W1 + (size_t)l * W1N * AD + 512 * AD;
        R = AD; C = HD;
    } else if (blk < 832) {
        blk -= 576; int l = blk >> 7; blk &= 127;
        src = mw1 + (size_t)l * AD * MD; dst = w16 + W_W1 + (size_t)l * W1N * AD;
        R = AD; C = MD;
    } else {
        blk -= 832; int l = blk >> 9; blk &= 511;
        src = mw2 + (size_t)l * MD * D; dst = w16 + W_W2 + (size_t)l * D * MD;
        R = MD; C = D;
    }
    int bx = blk % (C / 32), by = blk / (C / 32);
    tr_tile(src, dst, R, C, bx, by);
}

__global__ void pack_bias(const float* __restrict__ mw_b1, const float* __restrict__ sw_b1,
                          float* __restrict__ pb) {
    int i = blockIdx.x * blockDim.x + threadIdx.x;
    if (i < 2 * W1N) {
        int l = i / W1N, n = i % W1N;
        pb[i] = (n < MD) ? mw_b1[l * MD + n] : sw_b1[l * HD + n - MD];
    }
}

// ---------------- elementwise kernels ----------------
__global__ void init_kernel(const float* __restrict__ query,
                            __half* __restrict__ mat16, float* __restrict__ smooth,
                            __half* __restrict__ q16, __half* __restrict__ qm16,
                            size_t nbig, size_t nsm) {
    size_t i = ((size_t)blockIdx.x * blockDim.x + threadIdx.x) * 4;
    if (i < nbig) {
        float4 q = *(const float4*)(query + i);
        __half2 h0 = __floats2half2_rn(q.x, q.y);
        __half2 h1 = __floats2half2_rn(q.z, q.w);
        __half2 one2 = __floats2half2_rn(1.0f, 1.0f);
        *(__half2*)(q16 + i)      = h0;
        *(__half2*)(q16 + i + 2)  = h1;
        *(__half2*)(qm16 + i)     = h0;
        *(__half2*)(qm16 + i + 2) = h1;
        *(__half2*)(mat16 + i)     = one2;
        *(__half2*)(mat16 + i + 2) = one2;
    }
    if (i / 4 < nsm) smooth[i / 4] = 10.0f;
}

__global__ void l2norm256_kernel(const float* __restrict__ X, __half* __restrict__ Y) {
    int row = blockIdx.x * 8 + (threadIdx.x >> 5);
    int lane = threadIdx.x & 31;
    const float* p = X + (size_t)row * AD;
    float vals[8];
    float s = 0.0f;
#pragma unroll
    for (int j = 0; j < 8; j++) {
        vals[j] = p[lane + 32 * j];
        s += vals[j] * vals[j];
    }
    s = warp_sum(s);
    float inv = 1.0f / (sqrtf(s) + 1e-8f);
    __half* y = Y + (size_t)row * AD;
#pragma unroll
    for (int j = 0; j < 8; j++)
        y[lane + 32 * j] = __float2half_rn(vals[j] * inv);
}

__global__ void sw_reduce_kernel(const __half* __restrict__ hs, const float* __restrict__ w2,
                                 const float* __restrict__ b2, float* __restrict__ smooth)
{
    int row = blockIdx.x * 8 + (threadIdx.x >> 5);
    int lane = threadIdx.x & 31;
    const __half* r = hs + (size_t)row * W1N + MD;
    float s = __half2float(r[lane]) * w2[lane]
            + __half2float(r[lane + 32]) * w2[lane + 32]
            + __half2float(r[lane + 64]) * w2[lane + 64]
            + __half2float(r[lane + 96]) * w2[lane + 96];
    s = warp_sum(s);
    if (lane == 0) smooth[row] = fmaxf(0.0f, s + b2[0] + smooth[row]);
}

// ---------------- orchestration: two independent 64-batch pipelines ----------------
extern "C" void kernel_launch(void* const* d_in, const int* in_sizes, int n_in,
                              void* d_out, int out_size)
{
    const float* query = (const float*)d_in[0];
    const float* ctx   = (const float*)d_in[1];
    const float* cw_W  = (const float*)d_in[2];
    const float* cw_b  = (const float*)d_in[3];
    const float* sw_W1 = (const float*)d_in[4];
    const float* sw_b1 = (const float*)d_in[5];
    const float* sw_W2 = (const float*)d_in[6];
    const float* sw_b2 = (const float*)d_in[7];
    const float* mw_W1 = (const float*)d_in[8];
    const float* mw_b1 = (const float*)d_in[9];
    const float* mw_W2 = (const float*)d_in[10];
    const float* mw_b2 = (const float*)d_in[11];

    float* out      = (float*)d_out;
    float* out_q    = out;
    float* out_wc   = out + (size_t)Bb * NQ * D;
    float* out_attn = out + 2 * (size_t)Bb * NQ * D;

    float *psm, *pcom, *ppb;
    __half *pmat, *pq16, *pqm, *pctx16, *pctxT, *pattn16, *pd16, *pcom16, *phs16, *pw16;
    cudaGetSymbolAddress((void**)&psm,     g_smooth);
    cudaGetSymbolAddress((void**)&pcom,    g_common);
    cudaGetSymbolAddress((void**)&ppb,     g_pb);
    cudaGetSymbolAddress((void**)&pmat,    g_mat16);
    cudaGetSymbolAddress((void**)&pq16,    g_q16);
    cudaGetSymbolAddress((void**)&pqm,     g_qm16);
    cudaGetSymbolAddress((void**)&pctx16,  g_ctx16);
    cudaGetSymbolAddress((void**)&pctxT,   g_ctxT16);
    cudaGetSymbolAddress((void**)&pattn16, g_attn16);
    cudaGetSymbolAddress((void**)&pd16,    g_d16);
    cudaGetSymbolAddress((void**)&pcom16,  g_com16);
    cudaGetSymbolAddress((void**)&phs16,   g_hs16);
    cudaGetSymbolAddress((void**)&pw16,    g_w16);

    cudaFuncSetAttribute(hgemm<1>, cudaFuncAttributeMaxDynamicSharedMemorySize, SMEM_BYTES);
    cudaFuncSetAttribute(hgemm<2>, cudaFuncAttributeMaxDynamicSharedMemorySize, SMEM_BYTES);
    cudaFuncSetAttribute(hgemm<3>, cudaFuncAttributeMaxDynamicSharedMemorySize, SMEM_BYTES);
    cudaFuncSetAttribute(hgemm<4>, cudaFuncAttributeMaxDynamicSharedMemorySize, SMEM_BYTES);
    cudaFuncSetAttribute(hgemm<5>, cudaFuncAttributeMaxDynamicSharedMemorySize, SMEM_BYTES);
    cudaFuncSetAttribute(attn_fused, cudaFuncAttributeMaxDynamicSharedMemorySize, AT_SMEM);

    static cudaStream_t s1 = nullptr, s2 = nullptr;
    static cudaEvent_t evA = nullptr, evW = nullptr, evCpy = nullptr, evH1 = nullptr;
    if (s1 == nullptr) {
        cudaStreamCreateWithFlags(&s1, cudaStreamNonBlocking);
        cudaStreamCreateWithFlags(&s2, cudaStreamNonBlocking);
        cudaEventCreateWithFlags(&evA,   cudaEventDisableTiming);
        cudaEventCreateWithFlags(&evW,   cudaEventDisableTiming);
        cudaEventCreateWithFlags(&evCpy, cudaEventDisableTiming);
        cudaEventCreateWithFlags(&evH1,  cudaEventDisableTiming);
    }

    // fork side streams off the capture stream
    cudaEventRecord(evA, 0);
    cudaStreamWaitEvent(s1, evA, 0);
    cudaStreamWaitEvent(s2, evA, 0);

    // s2: shared weights prep + out_q copy
    transpose_weights<<<1856, dim3(32, 8), 0, s2>>>(cw_W, sw_W1, mw_W1, mw_W2, pw16);
    pack_bias<<<(2 * W1N + 255) / 256, 256, 0, s2>>>(mw_b1, sw_b1, ppb);
    cudaEventRecord(evW, s2);
    cudaMemcpyAsync(out_q, query, (size_t)Bb * NQ * D * sizeof(float),
                    cudaMemcpyDeviceToDevice, s2);
    cudaEventRecord(evCpy, s2);

    // per-half pipeline (fully independent per batch-half)
    auto run_half = [&](cudaStream_t st, int h) {
        const size_t oQ  = (size_t)h * BH * NQ * D;
        const size_t oC  = (size_t)h * BH * NC * D;
        const size_t oS  = (size_t)h * BH * NQ;
        const size_t oA  = (size_t)h * BH * NQ * NC;
        const size_t oCm = (size_t)h * BH * NQ * AD;
        const size_t oH  = (size_t)h * BH * NQ * W1N;

        // per-half prep (ctx convert + transpose fused into one pass)
        init_kernel<<<(BH * NQ * D / 4 + 255) / 256, 256, 0, st>>>(
            query + oQ, pmat + oQ, psm + oS, pq16 + oQ, pqm + oQ,
            (size_t)BH * NQ * D, (size_t)BH * NQ);
        ctx_prep<<<dim3(D / 32, NC / 32, BH), dim3(32, 8), 0, st>>>(
            ctx + oC, pctx16 + oC, pctxT + oC);

        // scan #0
        attn_fused<<<BH, 512, AT_SMEM, st>>>(pctx16 + oC, pqm + oQ, psm + oS,
                                             pattn16 + oA, nullptr);
        cudaStreamWaitEvent(st, evW, 0);

        for (int i = 0; i < 2; i++) {
            hgemm<1><<<dim3(8, 2, BH), 256, SMEM_BYTES, st>>>(
                pattn16 + oA, pctxT + oC, nullptr, pd16 + oQ, pq16 + oQ, nullptr, nullptr,
                NC, NC, D, (size_t)NQ * NC, (size_t)NC * D, (size_t)NQ * D);
            hgemm<3><<<dim3(2, BH * NQ / 128, 1), 256, SMEM_BYTES, st>>>(
                pd16 + oQ, pw16 + W_CW + (size_t)i * AD * D, cw_b + (size_t)i * AD,
                pcom + oCm, nullptr, nullptr, nullptr, D, D, AD, 0, 0, 0);
            l2norm256_kernel<<<BH * NQ / 8, 256, 0, st>>>(pcom + oCm, pcom16 + oCm);
            hgemm<4><<<dim3(5, BH * NQ / 128, 1), 256, SMEM_BYTES, st>>>(
                pcom16 + oCm, pw16 + W_W1 + (size_t)i * W1N * AD, ppb + (size_t)i * W1N,
                phs16 + oH, nullptr, nullptr, nullptr, AD, AD, W1N, 0, 0, 0);
            sw_reduce_kernel<<<BH * NQ / 8, 256, 0, st>>>(
                phs16 + oH, sw_W2 + (size_t)i * HD, sw_b2 + i, psm + oS);
            hgemm<5><<<dim3(8, BH * NQ / 128, 1), 256, SMEM_BYTES, st>>>(
                phs16 + oH, pw16 + W_W2 + (size_t)i * D * MD, mw_b2 + (size_t)i * D, nullptr,
                pq16 + oQ, pmat + oQ, pqm + oQ, MD, W1N, D, 0, 0, 0);
            attn_fused<<<BH, 512, AT_SMEM, st>>>(
                pctx16 + oC, pqm + oQ, psm + oS, pattn16 + oA,
                (i == 1) ? (out_attn + oA) : nullptr);
        }

        hgemm<2><<<dim3(8, 2, BH), 256, SMEM_BYTES, st>>>(
            pattn16 + oA, pctxT + oC, nullptr, out_wc + oQ, nullptr, nullptr, nullptr,
            NC, NC, D, (size_t)NQ * NC, (size_t)NC * D, (size_t)NQ * D);
    };

    run_half((cudaStream_t)0, 0);   // half 0 on the capture stream
    run_half(s1, 1);                // half 1 on side stream

    // join: capture stream waits for half 1 and the out_q copy
    cudaEventRecord(evH1, s1);
    cudaStreamWaitEvent(0, evH1, 0);
    cudaStreamWaitEvent(0, evCpy, 0);
}